// round 2
// baseline (speedup 1.0000x reference)
#include <cuda_runtime.h>

#define Dd 64
#define Hh 128
#define Ww 128
#define HW (Hh*Ww)
#define NN (Dd*Hh*Ww)

// ---------------- scratch (device globals: alloc-free, capture-safe) ----------
__device__ float g_t[NN];
__device__ float g_z[NN];
__device__ float g_p[NN];
__device__ float g_q[NN];
__device__ float g_s[NN];
__device__ float g_zp[NN];
__device__ float g_sums[HW];
__device__ float g_h1[16*NN];
__device__ float g_h2[16*NN];

// ---------------- packed f32x2 helpers (FFMA2: 2 FMAs per issue slot) ---------
static __device__ __forceinline__ unsigned long long pack2(float lo, float hi){
    unsigned long long r;
    asm("mov.b64 %0, {%1,%2};" : "=l"(r) : "f"(lo), "f"(hi));
    return r;
}
static __device__ __forceinline__ void unpack2(unsigned long long v, float &lo, float &hi){
    asm("mov.b64 {%0,%1}, %2;" : "=f"(lo), "=f"(hi) : "l"(v));
}
static __device__ __forceinline__ void ffma2(unsigned long long &d, unsigned long long a, unsigned long long b){
    asm("fma.rn.f32x2 %0, %1, %2, %0;" : "+l"(d) : "l"(a), "l"(b));
}

// x = fdiff(z, axis) evaluated on the fly (0:W, 1:H, 2:D, 3:identity),
// zero outside the volume (conv SAME padding) and at the fdiff tail.
template<int MODE>
static __device__ __forceinline__ float getx(int d, int h, int w){
    if (d < 0 || d >= Dd || h < 0 || h >= Hh || w < 0 || w >= Ww) return 0.f;
    int idx = (d*Hh + h)*Ww + w;
    if (MODE == 0) return (w < Ww-1) ? g_z[idx+1]  - g_z[idx] : 0.f;
    if (MODE == 1) return (h < Hh-1) ? g_z[idx+Ww] - g_z[idx] : 0.f;
    if (MODE == 2) return (d < Dd-1) ? g_z[idx+HW] - g_z[idx] : 0.f;
    return g_z[idx];
}

// ---------------- init: t = image, outs[0] = image, p=q=s=0 -------------------
__global__ void k_init(const float* __restrict__ img, float* __restrict__ outp){
    int idx = blockIdx.x*256 + threadIdx.x;
    float v = img[idx];
    g_t[idx] = v;
    outp[idx] = v;
    g_p[idx] = 0.f; g_q[idx] = 0.f; g_s[idx] = 0.f;
}

// ---------------- column sum over D ------------------------------------------
__global__ void k_colsum(){
    int j = blockIdx.x*256 + threadIdx.x;     // 0..HW-1
    float a0=0.f, a1=0.f, a2=0.f, a3=0.f;
    #pragma unroll
    for (int d = 0; d < Dd; d += 4){
        a0 += g_t[(d+0)*HW + j];
        a1 += g_t[(d+1)*HW + j];
        a2 += g_t[(d+2)*HW + j];
        a3 += g_t[(d+3)*HW + j];
    }
    g_sums[j] = (a0+a1)+(a2+a3);
}

// ---------------- z = t + (sino - colsum)/D -----------------------------------
__global__ void k_z(const float* __restrict__ sino){
    int idx = blockIdx.x*256 + threadIdx.x;
    int j = idx & (HW-1);
    g_z[idx] = g_t[idx] + (sino[j] - g_sums[j]) * (1.f/64.f);
}

// ================= conv1: 1 -> 16, fused fdiff input, relu, -> g_h1 ===========
// tile: 4(d) x 8(h) x 32(w) outputs, all 16 co. 256 threads = (32,8).
template<int MODE>
__global__ void __launch_bounds__(256) k_conv1(const float* __restrict__ w1,
                                               const float* __restrict__ b1){
    __shared__ float sx[2040];                          // 6 x 10 x 34 halo tile
    __shared__ __align__(16) unsigned long long swt[216]; // 27 k x 8 co-pairs
    const int tx = threadIdx.x, ty = threadIdx.y;
    const int tid = ty*32 + tx;
    const int w0 = blockIdx.x*32, h0 = blockIdx.y*8, d0 = blockIdx.z*4;

    if (tid < 216){
        int cp = tid & 7, k = tid >> 3;
        swt[tid] = pack2(w1[(2*cp)*27 + k], w1[(2*cp+1)*27 + k]);
    }
    for (int i = tid; i < 2040; i += 256){
        int xx = i % 34; int r = i / 34;
        int yy = r % 10; int dz = r / 10;
        sx[i] = getx<MODE>(d0-1+dz, h0-1+yy, w0-1+xx);
    }
    __syncthreads();

    unsigned long long acc[4][8];
    #pragma unroll
    for (int dz=0; dz<4; dz++)
        #pragma unroll
        for (int cp=0; cp<8; cp++) acc[dz][cp] = 0ull;

    const float* bx = sx + ty*34 + tx;
    #pragma unroll
    for (int kh=0; kh<3; kh++)
    #pragma unroll
    for (int kw=0; kw<3; kw++){
        unsigned long long x2[6];
        #pragma unroll
        for (int j=0; j<6; j++){
            float xv = bx[j*340 + kh*34 + kw];
            x2[j] = pack2(xv, xv);
        }
        #pragma unroll
        for (int kd=0; kd<3; kd++){
            const int k = (kd*3+kh)*3+kw;
            const ulonglong2* wp = reinterpret_cast<const ulonglong2*>(swt + k*8);
            #pragma unroll
            for (int jp=0; jp<4; jp++){
                ulonglong2 wv = wp[jp];
                #pragma unroll
                for (int dz=0; dz<4; dz++){
                    ffma2(acc[dz][2*jp],   x2[dz+kd], wv.x);
                    ffma2(acc[dz][2*jp+1], x2[dz+kd], wv.y);
                }
            }
        }
    }

    const int hh = h0+ty, ww = w0+tx;
    #pragma unroll
    for (int cp=0; cp<8; cp++){
        float bl = b1[2*cp], bh = b1[2*cp+1];
        #pragma unroll
        for (int dz=0; dz<4; dz++){
            float lo, hi; unpack2(acc[dz][cp], lo, hi);
            int idx = ((d0+dz)*Hh + hh)*Ww + ww;
            g_h1[(2*cp)*NN + idx]   = fmaxf(lo + bl, 0.f);
            g_h1[(2*cp+1)*NN + idx] = fmaxf(hi + bh, 0.f);
        }
    }
}

// ================= conv2: 16 -> 16, relu, g_h1 -> g_h2 (hot kernel) ===========
__global__ void __launch_bounds__(256) k_conv2(const float* __restrict__ w2,
                                               const float* __restrict__ b2){
    __shared__ float sx[4*2040];                          // 4 ci x (6 x 10 x 34)
    __shared__ __align__(16) unsigned long long swt[4*216]; // 4 ci x 27 k x 8 cp
    const int tx = threadIdx.x, ty = threadIdx.y;
    const int tid = ty*32 + tx;
    const int w0 = blockIdx.x*32, h0 = blockIdx.y*8, d0 = blockIdx.z*4;

    unsigned long long acc[4][8];
    #pragma unroll
    for (int dz=0; dz<4; dz++)
        #pragma unroll
        for (int cp=0; cp<8; cp++) acc[dz][cp] = 0ull;

    for (int cc = 0; cc < 4; cc++){
        __syncthreads();
        for (int i = tid; i < 864; i += 256){
            int cp = i & 7, k = (i >> 3) % 27, ci4 = i / 216;
            int ci = cc*4 + ci4;
            swt[i] = pack2(w2[((2*cp)*16 + ci)*27 + k],
                           w2[((2*cp+1)*16 + ci)*27 + k]);
        }
        for (int i = tid; i < 8160; i += 256){
            int xx = i % 34; int r = i / 34;
            int yy = r % 10; int r2 = r / 10;
            int dz = r2 % 6; int ci4 = r2 / 6;
            int d = d0-1+dz, h = h0-1+yy, w = w0-1+xx;
            float v = 0.f;
            if (d >= 0 && d < Dd && h >= 0 && h < Hh && w >= 0 && w < Ww)
                v = g_h1[(cc*4 + ci4)*NN + (d*Hh + h)*Ww + w];
            sx[i] = v;
        }
        __syncthreads();

        #pragma unroll 1
        for (int ci4 = 0; ci4 < 4; ci4++){
            const float* bx = sx + ci4*2040 + ty*34 + tx;
            const unsigned long long* bw = swt + ci4*216;
            #pragma unroll
            for (int kh=0; kh<3; kh++)
            #pragma unroll
            for (int kw=0; kw<3; kw++){
                unsigned long long x2[6];
                #pragma unroll
                for (int j=0; j<6; j++){
                    float xv = bx[j*340 + kh*34 + kw];
                    x2[j] = pack2(xv, xv);
                }
                #pragma unroll
                for (int kd=0; kd<3; kd++){
                    const int k = (kd*3+kh)*3+kw;
                    const ulonglong2* wp = reinterpret_cast<const ulonglong2*>(bw + k*8);
                    #pragma unroll
                    for (int jp=0; jp<4; jp++){
                        ulonglong2 wv = wp[jp];
                        #pragma unroll
                        for (int dz=0; dz<4; dz++){
                            ffma2(acc[dz][2*jp],   x2[dz+kd], wv.x);
                            ffma2(acc[dz][2*jp+1], x2[dz+kd], wv.y);
                        }
                    }
                }
            }
        }
    }

    const int hh = h0+ty, ww = w0+tx;
    #pragma unroll
    for (int cp=0; cp<8; cp++){
        float bl = b2[2*cp], bh = b2[2*cp+1];
        #pragma unroll
        for (int dz=0; dz<4; dz++){
            float lo, hi; unpack2(acc[dz][cp], lo, hi);
            int idx = ((d0+dz)*Hh + hh)*Ww + ww;
            g_h2[(2*cp)*NN + idx]   = fmaxf(lo + bl, 0.f);
            g_h2[(2*cp+1)*NN + idx] = fmaxf(hi + bh, 0.f);
        }
    }
}

// ================= conv3: 16 -> 1, fused residual + p/q/s/z' update ===========
// A=0: p update (ntx), A=1: q (nty), A=2: s (ntz), A=3: z' = (1+nt)t - nt*znew
template<int A>
__global__ void __launch_bounds__(256) k_conv3(const float* __restrict__ w3,
                                               const float* __restrict__ b3,
                                               const float* __restrict__ eta_arr,
                                               int c){
    __shared__ float sx[4*2040];
    __shared__ float swt[108];                 // 4 ci x 27 k
    const int tx = threadIdx.x, ty = threadIdx.y;
    const int tid = ty*32 + tx;
    const int w0 = blockIdx.x*32, h0 = blockIdx.y*8, d0 = blockIdx.z*4;

    unsigned long long acc2[2] = {0ull, 0ull};   // (dz0,dz1), (dz2,dz3)

    for (int cc = 0; cc < 4; cc++){
        __syncthreads();
        if (tid < 108){
            int k = tid % 27, ci4 = tid / 27;
            swt[tid] = w3[(cc*4 + ci4)*27 + k];
        }
        for (int i = tid; i < 8160; i += 256){
            int xx = i % 34; int r = i / 34;
            int yy = r % 10; int r2 = r / 10;
            int dz = r2 % 6; int ci4 = r2 / 6;
            int d = d0-1+dz, h = h0-1+yy, w = w0-1+xx;
            float v = 0.f;
            if (d >= 0 && d < Dd && h >= 0 && h < Hh && w >= 0 && w < Ww)
                v = g_h2[(cc*4 + ci4)*NN + (d*Hh + h)*Ww + w];
            sx[i] = v;
        }
        __syncthreads();

        #pragma unroll 1
        for (int ci4 = 0; ci4 < 4; ci4++){
            const float* bx = sx + ci4*2040 + ty*34 + tx;
            const float* bw = swt + ci4*27;
            #pragma unroll
            for (int kh=0; kh<3; kh++)
            #pragma unroll
            for (int kw=0; kw<3; kw++){
                float xv[6];
                #pragma unroll
                for (int j=0; j<6; j++) xv[j] = bx[j*340 + kh*34 + kw];
                unsigned long long xp[5];
                #pragma unroll
                for (int j=0; j<5; j++) xp[j] = pack2(xv[j], xv[j+1]);
                #pragma unroll
                for (int kd=0; kd<3; kd++){
                    float wv = bw[(kd*3+kh)*3+kw];
                    unsigned long long wv2 = pack2(wv, wv);
                    ffma2(acc2[0], xp[kd],   wv2);
                    ffma2(acc2[1], xp[kd+2], wv2);
                }
            }
        }
    }

    float accd[4];
    unpack2(acc2[0], accd[0], accd[1]);
    unpack2(acc2[1], accd[2], accd[3]);

    float* tgt        = (A==0) ? g_p : (A==1) ? g_q : (A==2) ? g_s : g_zp;
    const float* base = (A==3) ? g_t : tgt;
    const float eta = eta_arr[c];
    const float b3v = b3[0];
    const int hh = h0+ty, ww = w0+tx;
    #pragma unroll
    for (int dz=0; dz<4; dz++){
        int d = d0+dz;
        int idx = (d*Hh + hh)*Ww + ww;
        float nnew = getx<A>(d, hh, ww) + accd[dz] + b3v;  // basic_block residual
        tgt[idx] = (1.f + eta)*base[idx] - eta*nnew;       // u + eta*(u - unew)
    }
}

// ---------------- update: t = fdT_w(p)+fdT_h(q)+fdT_d(s)+z', write out --------
__global__ void k_update(float* __restrict__ outp){
    int idx = blockIdx.x*256 + threadIdx.x;
    int w = idx & (Ww-1);
    int h = (idx >> 7) & (Hh-1);
    int d = idx >> 14;
    float fa = (w==Ww-1) ? g_p[idx-1]  : ((w>0 ? g_p[idx-1]  : 0.f) - g_p[idx]);
    float fb = (h==Hh-1) ? g_q[idx-Ww] : ((h>0 ? g_q[idx-Ww] : 0.f) - g_q[idx]);
    float fc = (d==Dd-1) ? g_s[idx-HW] : ((d>0 ? g_s[idx-HW] : 0.f) - g_s[idx]);
    float tn = fa + fb + fc + g_zp[idx];
    g_t[idx] = tn;
    outp[idx] = tn;
}

// ---------------- launcher -----------------------------------------------------
extern "C" void kernel_launch(void* const* d_in, const int* in_sizes, int n_in,
                              void* d_out, int out_size){
    (void)in_sizes; (void)n_in; (void)out_size;
    const float* img  = (const float*)d_in[0];
    const float* sino = (const float*)d_in[1];
    const float* w1   = (const float*)d_in[2];
    const float* b1   = (const float*)d_in[3];
    const float* w2   = (const float*)d_in[4];
    const float* b2   = (const float*)d_in[5];
    const float* w3   = (const float*)d_in[6];
    const float* b3   = (const float*)d_in[7];
    const float* ntx  = (const float*)d_in[8];
    const float* nty  = (const float*)d_in[9];
    const float* ntz  = (const float*)d_in[10];
    const float* nt   = (const float*)d_in[11];
    float* out = (float*)d_out;

    dim3 cg(4, 16, 16), cb(32, 8, 1);
    k_init<<<NN/256, 256>>>(img, out);
    for (int c = 0; c < 3; c++){
        k_colsum<<<HW/256, 256>>>();
        k_z<<<NN/256, 256>>>(sino);

        k_conv1<0><<<cg, cb>>>(w1 + 0*432, b1 + 0*16);
        k_conv2<<<cg, cb>>>(w2 + 0*6912, b2 + 0*16);
        k_conv3<0><<<cg, cb>>>(w3 + 0*432, b3 + 0, ntx, c);

        k_conv1<1><<<cg, cb>>>(w1 + 1*432, b1 + 1*16);
        k_conv2<<<cg, cb>>>(w2 + 1*6912, b2 + 1*16);
        k_conv3<1><<<cg, cb>>>(w3 + 1*432, b3 + 1, nty, c);

        k_conv1<2><<<cg, cb>>>(w1 + 2*432, b1 + 2*16);
        k_conv2<<<cg, cb>>>(w2 + 2*6912, b2 + 2*16);
        k_conv3<2><<<cg, cb>>>(w3 + 2*432, b3 + 2, ntz, c);

        k_conv1<3><<<cg, cb>>>(w1 + 3*432, b1 + 3*16);
        k_conv2<<<cg, cb>>>(w2 + 3*6912, b2 + 3*16);
        k_conv3<3><<<cg, cb>>>(w3 + 3*432, b3 + 3, nt, c);

        k_update<<<NN/256, 256>>>(out + (c+1)*NN);
    }
}

// round 3
// speedup vs baseline: 1.5676x; 1.5676x over previous
#include <cuda_runtime.h>

#define Dd 64
#define Hh 128
#define Ww 128
#define HW (Hh*Ww)
#define NN (Dd*Hh*Ww)

// ---------------- scratch (device globals: alloc-free, capture-safe) ----------
__device__ float g_t[NN];
__device__ float g_z[NN];
__device__ float g_p[NN];
__device__ float g_q[NN];
__device__ float g_s[NN];
__device__ float g_zp[NN];
__device__ float g_sums[HW];
__device__ float g_h1[16*NN];
__device__ float g_h2[16*NN];

// ---------------- packed f32x2 helpers (FFMA2: 2 FMAs per issue slot) ---------
static __device__ __forceinline__ unsigned long long pack2(float lo, float hi){
    unsigned long long r;
    asm("mov.b64 %0, {%1,%2};" : "=l"(r) : "f"(lo), "f"(hi));
    return r;
}
static __device__ __forceinline__ void unpack2(unsigned long long v, float &lo, float &hi){
    asm("mov.b64 {%0,%1}, %2;" : "=f"(lo), "=f"(hi) : "l"(v));
}
static __device__ __forceinline__ void ffma2(unsigned long long &d, unsigned long long a, unsigned long long b){
    asm("fma.rn.f32x2 %0, %1, %2, %0;" : "+l"(d) : "l"(a), "l"(b));
}

// x = fdiff(z, axis) evaluated on the fly (0:W, 1:H, 2:D, 3:identity),
// zero outside the volume (conv SAME padding) and at the fdiff tail.
template<int MODE>
static __device__ __forceinline__ float getx(int d, int h, int w){
    if (d < 0 || d >= Dd || h < 0 || h >= Hh || w < 0 || w >= Ww) return 0.f;
    int idx = (d*Hh + h)*Ww + w;
    if (MODE == 0) return (w < Ww-1) ? g_z[idx+1]  - g_z[idx] : 0.f;
    if (MODE == 1) return (h < Hh-1) ? g_z[idx+Ww] - g_z[idx] : 0.f;
    if (MODE == 2) return (d < Dd-1) ? g_z[idx+HW] - g_z[idx] : 0.f;
    return g_z[idx];
}

// ---------------- init: t = image, outs[0] = image, p=q=s=0 -------------------
__global__ void k_init(const float* __restrict__ img, float* __restrict__ outp){
    int idx = blockIdx.x*256 + threadIdx.x;
    float v = img[idx];
    g_t[idx] = v;
    outp[idx] = v;
    g_p[idx] = 0.f; g_q[idx] = 0.f; g_s[idx] = 0.f;
}

// ---------------- column sum over D ------------------------------------------
__global__ void k_colsum(){
    int j = blockIdx.x*256 + threadIdx.x;     // 0..HW-1
    float a0=0.f, a1=0.f, a2=0.f, a3=0.f;
    #pragma unroll
    for (int d = 0; d < Dd; d += 4){
        a0 += g_t[(d+0)*HW + j];
        a1 += g_t[(d+1)*HW + j];
        a2 += g_t[(d+2)*HW + j];
        a3 += g_t[(d+3)*HW + j];
    }
    g_sums[j] = (a0+a1)+(a2+a3);
}

// ---------------- z = t + (sino - colsum)/D -----------------------------------
__global__ void k_z(const float* __restrict__ sino){
    int idx = blockIdx.x*256 + threadIdx.x;
    int j = idx & (HW-1);
    g_z[idx] = g_t[idx] + (sino[j] - g_sums[j]) * (1.f/64.f);
}

// ================= conv1: 1 -> 16, fused fdiff input, relu, -> g_h1 ===========
// tile: 4(d) x 8(h) x 32(w) outputs, all 16 co. 256 threads = (32,8).
template<int MODE>
__global__ void __launch_bounds__(256) k_conv1(const float* __restrict__ w1,
                                               const float* __restrict__ b1){
    __shared__ float sx[2040];                          // 6 x 10 x 34 halo tile
    __shared__ __align__(16) unsigned long long swt[216]; // 27 k x 8 co-pairs
    const int tx = threadIdx.x, ty = threadIdx.y;
    const int tid = ty*32 + tx;
    const int w0 = blockIdx.x*32, h0 = blockIdx.y*8, d0 = blockIdx.z*4;

    if (tid < 216){
        int cp = tid & 7, k = tid >> 3;
        swt[tid] = pack2(w1[(2*cp)*27 + k], w1[(2*cp+1)*27 + k]);
    }
    for (int i = tid; i < 2040; i += 256){
        int xx = i % 34; int r = i / 34;
        int yy = r % 10; int dz = r / 10;
        sx[i] = getx<MODE>(d0-1+dz, h0-1+yy, w0-1+xx);
    }
    __syncthreads();

    unsigned long long acc[4][8];
    #pragma unroll
    for (int dz=0; dz<4; dz++)
        #pragma unroll
        for (int cp=0; cp<8; cp++) acc[dz][cp] = 0ull;

    const float* bx = sx + ty*34 + tx;
    #pragma unroll
    for (int kh=0; kh<3; kh++)
    #pragma unroll
    for (int kw=0; kw<3; kw++){
        unsigned long long x2[6];
        #pragma unroll
        for (int j=0; j<6; j++){
            float xv = bx[j*340 + kh*34 + kw];
            x2[j] = pack2(xv, xv);
        }
        #pragma unroll
        for (int kd=0; kd<3; kd++){
            const int k = (kd*3+kh)*3+kw;
            const ulonglong2* wp = reinterpret_cast<const ulonglong2*>(swt + k*8);
            #pragma unroll
            for (int jp=0; jp<4; jp++){
                ulonglong2 wv = wp[jp];
                #pragma unroll
                for (int dz=0; dz<4; dz++){
                    ffma2(acc[dz][2*jp],   x2[dz+kd], wv.x);
                    ffma2(acc[dz][2*jp+1], x2[dz+kd], wv.y);
                }
            }
        }
    }

    const int hh = h0+ty, ww = w0+tx;
    #pragma unroll
    for (int cp=0; cp<8; cp++){
        float bl = b1[2*cp], bh = b1[2*cp+1];
        #pragma unroll
        for (int dz=0; dz<4; dz++){
            float lo, hi; unpack2(acc[dz][cp], lo, hi);
            int idx = ((d0+dz)*Hh + hh)*Ww + ww;
            g_h1[(2*cp)*NN + idx]   = fmaxf(lo + bl, 0.f);
            g_h1[(2*cp+1)*NN + idx] = fmaxf(hi + bh, 0.f);
        }
    }
}

// ================= conv2: 16 -> 16, relu, g_h1 -> g_h2 (hot kernel) ===========
__global__ void __launch_bounds__(256) k_conv2(const float* __restrict__ w2,
                                               const float* __restrict__ b2){
    __shared__ float sx[4*2040];                          // 4 ci x (6 x 10 x 34)
    __shared__ __align__(16) unsigned long long swt[4*216]; // 4 ci x 27 k x 8 cp
    const int tx = threadIdx.x, ty = threadIdx.y;
    const int tid = ty*32 + tx;
    const int w0 = blockIdx.x*32, h0 = blockIdx.y*8, d0 = blockIdx.z*4;

    unsigned long long acc[4][8];
    #pragma unroll
    for (int dz=0; dz<4; dz++)
        #pragma unroll
        for (int cp=0; cp<8; cp++) acc[dz][cp] = 0ull;

    for (int cc = 0; cc < 4; cc++){
        __syncthreads();
        for (int i = tid; i < 864; i += 256){
            int cp = i & 7, k = (i >> 3) % 27, ci4 = i / 216;
            int ci = cc*4 + ci4;
            swt[i] = pack2(w2[((2*cp)*16 + ci)*27 + k],
                           w2[((2*cp+1)*16 + ci)*27 + k]);
        }
        for (int i = tid; i < 8160; i += 256){
            int xx = i % 34; int r = i / 34;
            int yy = r % 10; int r2 = r / 10;
            int dz = r2 % 6; int ci4 = r2 / 6;
            int d = d0-1+dz, h = h0-1+yy, w = w0-1+xx;
            float v = 0.f;
            if (d >= 0 && d < Dd && h >= 0 && h < Hh && w >= 0 && w < Ww)
                v = g_h1[(cc*4 + ci4)*NN + (d*Hh + h)*Ww + w];
            sx[i] = v;
        }
        __syncthreads();

        #pragma unroll 1
        for (int ci4 = 0; ci4 < 4; ci4++){
            const float* bx = sx + ci4*2040 + ty*34 + tx;
            const unsigned long long* bw = swt + ci4*216;
            #pragma unroll
            for (int kh=0; kh<3; kh++)
            #pragma unroll
            for (int kw=0; kw<3; kw++){
                unsigned long long x2[6];
                #pragma unroll
                for (int j=0; j<6; j++){
                    float xv = bx[j*340 + kh*34 + kw];
                    x2[j] = pack2(xv, xv);
                }
                #pragma unroll
                for (int kd=0; kd<3; kd++){
                    const int k = (kd*3+kh)*3+kw;
                    const ulonglong2* wp = reinterpret_cast<const ulonglong2*>(bw + k*8);
                    #pragma unroll
                    for (int jp=0; jp<4; jp++){
                        ulonglong2 wv = wp[jp];
                        #pragma unroll
                        for (int dz=0; dz<4; dz++){
                            ffma2(acc[dz][2*jp],   x2[dz+kd], wv.x);
                            ffma2(acc[dz][2*jp+1], x2[dz+kd], wv.y);
                        }
                    }
                }
            }
        }
    }

    const int hh = h0+ty, ww = w0+tx;
    #pragma unroll
    for (int cp=0; cp<8; cp++){
        float bl = b2[2*cp], bh = b2[2*cp+1];
        #pragma unroll
        for (int dz=0; dz<4; dz++){
            float lo, hi; unpack2(acc[dz][cp], lo, hi);
            int idx = ((d0+dz)*Hh + hh)*Ww + ww;
            g_h2[(2*cp)*NN + idx]   = fmaxf(lo + bl, 0.f);
            g_h2[(2*cp+1)*NN + idx] = fmaxf(hi + bh, 0.f);
        }
    }
}

// ================= conv3: 16 -> 1, fused residual + p/q/s/z' update ===========
// A=0: p update (ntx), A=1: q (nty), A=2: s (ntz), A=3: z' = (1+nt)t - nt*znew
template<int A>
__global__ void __launch_bounds__(256) k_conv3(const float* __restrict__ w3,
                                               const float* __restrict__ b3,
                                               const float* __restrict__ eta_arr,
                                               int c){
    __shared__ float sx[4*2040];
    __shared__ float swt[108];                 // 4 ci x 27 k
    const int tx = threadIdx.x, ty = threadIdx.y;
    const int tid = ty*32 + tx;
    const int w0 = blockIdx.x*32, h0 = blockIdx.y*8, d0 = blockIdx.z*4;

    unsigned long long acc2[2] = {0ull, 0ull};   // (dz0,dz1), (dz2,dz3)

    for (int cc = 0; cc < 4; cc++){
        __syncthreads();
        if (tid < 108){
            int k = tid % 27, ci4 = tid / 27;
            swt[tid] = w3[(cc*4 + ci4)*27 + k];
        }
        for (int i = tid; i < 8160; i += 256){
            int xx = i % 34; int r = i / 34;
            int yy = r % 10; int r2 = r / 10;
            int dz = r2 % 6; int ci4 = r2 / 6;
            int d = d0-1+dz, h = h0-1+yy, w = w0-1+xx;
            float v = 0.f;
            if (d >= 0 && d < Dd && h >= 0 && h < Hh && w >= 0 && w < Ww)
                v = g_h2[(cc*4 + ci4)*NN + (d*Hh + h)*Ww + w];
            sx[i] = v;
        }
        __syncthreads();

        #pragma unroll 1
        for (int ci4 = 0; ci4 < 4; ci4++){
            const float* bx = sx + ci4*2040 + ty*34 + tx;
            const float* bw = swt + ci4*27;
            #pragma unroll
            for (int kh=0; kh<3; kh++)
            #pragma unroll
            for (int kw=0; kw<3; kw++){
                float xv[6];
                #pragma unroll
                for (int j=0; j<6; j++) xv[j] = bx[j*340 + kh*34 + kw];
                unsigned long long xp[5];
                #pragma unroll
                for (int j=0; j<5; j++) xp[j] = pack2(xv[j], xv[j+1]);
                #pragma unroll
                for (int kd=0; kd<3; kd++){
                    float wv = bw[(kd*3+kh)*3+kw];
                    unsigned long long wv2 = pack2(wv, wv);
                    ffma2(acc2[0], xp[kd],   wv2);
                    ffma2(acc2[1], xp[kd+2], wv2);
                }
            }
        }
    }

    float accd[4];
    unpack2(acc2[0], accd[0], accd[1]);
    unpack2(acc2[1], accd[2], accd[3]);

    float* tgt        = (A==0) ? g_p : (A==1) ? g_q : (A==2) ? g_s : g_zp;
    const float* base = (A==3) ? g_t : tgt;
    const float eta = eta_arr[c];
    const float b3v = b3[0];
    const int hh = h0+ty, ww = w0+tx;
    #pragma unroll
    for (int dz=0; dz<4; dz++){
        int d = d0+dz;
        int idx = (d*Hh + hh)*Ww + ww;
        float nnew = getx<A>(d, hh, ww) + accd[dz] + b3v;  // basic_block residual
        tgt[idx] = (1.f + eta)*base[idx] - eta*nnew;       // u + eta*(u - unew)
    }
}

// ---------------- update: t = fdT_w(p)+fdT_h(q)+fdT_d(s)+z', write out --------
__global__ void k_update(float* __restrict__ outp){
    int idx = blockIdx.x*256 + threadIdx.x;
    int w = idx & (Ww-1);
    int h = (idx >> 7) & (Hh-1);
    int d = idx >> 14;
    float fa = (w==Ww-1) ? g_p[idx-1]  : ((w>0 ? g_p[idx-1]  : 0.f) - g_p[idx]);
    float fb = (h==Hh-1) ? g_q[idx-Ww] : ((h>0 ? g_q[idx-Ww] : 0.f) - g_q[idx]);
    float fc = (d==Dd-1) ? g_s[idx-HW] : ((d>0 ? g_s[idx-HW] : 0.f) - g_s[idx]);
    float tn = fa + fb + fc + g_zp[idx];
    g_t[idx] = tn;
    outp[idx] = tn;
}

// ---------------- launcher -----------------------------------------------------
extern "C" void kernel_launch(void* const* d_in, const int* in_sizes, int n_in,
                              void* d_out, int out_size){
    (void)in_sizes; (void)n_in; (void)out_size;
    const float* img  = (const float*)d_in[0];
    const float* sino = (const float*)d_in[1];
    const float* w1   = (const float*)d_in[2];
    const float* b1   = (const float*)d_in[3];
    const float* w2   = (const float*)d_in[4];
    const float* b2   = (const float*)d_in[5];
    const float* w3   = (const float*)d_in[6];
    const float* b3   = (const float*)d_in[7];
    const float* ntx  = (const float*)d_in[8];
    const float* nty  = (const float*)d_in[9];
    const float* ntz  = (const float*)d_in[10];
    const float* nt   = (const float*)d_in[11];
    float* out = (float*)d_out;

    dim3 cg(4, 16, 16), cb(32, 8, 1);
    k_init<<<NN/256, 256>>>(img, out);
    for (int c = 0; c < 3; c++){
        k_colsum<<<HW/256, 256>>>();
        k_z<<<NN/256, 256>>>(sino);

        k_conv1<0><<<cg, cb>>>(w1 + 0*432, b1 + 0*16);
        k_conv2<<<cg, cb>>>(w2 + 0*6912, b2 + 0*16);
        k_conv3<0><<<cg, cb>>>(w3 + 0*432, b3 + 0, ntx, c);

        k_conv1<1><<<cg, cb>>>(w1 + 1*432, b1 + 1*16);
        k_conv2<<<cg, cb>>>(w2 + 1*6912, b2 + 1*16);
        k_conv3<1><<<cg, cb>>>(w3 + 1*432, b3 + 1, nty, c);

        k_conv1<2><<<cg, cb>>>(w1 + 2*432, b1 + 2*16);
        k_conv2<<<cg, cb>>>(w2 + 2*6912, b2 + 2*16);
        k_conv3<2><<<cg, cb>>>(w3 + 2*432, b3 + 2, ntz, c);

        k_conv1<3><<<cg, cb>>>(w1 + 3*432, b1 + 3*16);
        k_conv2<<<cg, cb>>>(w2 + 3*6912, b2 + 3*16);
        k_conv3<3><<<cg, cb>>>(w3 + 3*432, b3 + 3, nt, c);

        k_update<<<NN/256, 256>>>(out + (c+1)*NN);
    }
}

// round 5
// speedup vs baseline: 1.9863x; 1.2671x over previous
#include <cuda_runtime.h>
#include <cstdint>

#define Dd 64
#define Hh 128
#define Ww 128
#define HW (Hh*Ww)
#define NN (Dd*Hh*Ww)

// ---------------- scratch (device globals: alloc-free, capture-safe) ----------
__device__ float g_t[NN];
__device__ float g_z[NN];
__device__ float g_p[NN];
__device__ float g_q[NN];
__device__ float g_s[NN];
__device__ float g_zp[NN];
__device__ float g_sums[HW];
__device__ float g_h1[16*NN];   // channel-interleaved: [pos][16 ci]
__device__ float g_h2[16*NN];   // channel-interleaved: [pos][16 ci]

// ---------------- packed f32x2 helpers -----------------------------------------
static __device__ __forceinline__ unsigned long long pack2(float lo, float hi){
    unsigned long long r;
    asm("mov.b64 %0, {%1,%2};" : "=l"(r) : "f"(lo), "f"(hi));
    return r;
}
static __device__ __forceinline__ void unpack2(unsigned long long v, float &lo, float &hi){
    asm("mov.b64 {%0,%1}, %2;" : "=f"(lo), "=f"(hi) : "l"(v));
}
static __device__ __forceinline__ void ffma2(unsigned long long &d, unsigned long long a, unsigned long long b){
    asm("fma.rn.f32x2 %0, %1, %2, %0;" : "+l"(d) : "l"(a), "l"(b));
}

// ---------------- mma.sync helpers (family-safe PTX, sm_80+) --------------------
static __device__ __forceinline__ uint32_t smem_u32(const void* p){
    uint32_t a;
    asm("{ .reg .u64 t; cvta.to.shared.u64 t, %1; cvt.u32.u64 %0, t; }" : "=r"(a) : "l"(p));
    return a;
}
static __device__ __forceinline__ uint32_t f2tf32(float x){
    uint32_t r;
    asm("cvt.rna.tf32.f32 %0, %1;" : "=r"(r) : "f"(x));
    return r;
}
static __device__ __forceinline__ void lds_v2(uint32_t addr, uint32_t &x, uint32_t &y){
    asm volatile("ld.shared.v2.u32 {%0,%1}, [%2];" : "=r"(x), "=r"(y) : "r"(addr));
}
static __device__ __forceinline__ void mma_tf32(float* c, uint32_t a0, uint32_t a1,
                                                uint32_t a2, uint32_t a3,
                                                uint32_t b0, uint32_t b1){
    asm volatile(
        "mma.sync.aligned.m16n8k8.row.col.f32.tf32.tf32.f32 "
        "{%0,%1,%2,%3}, {%4,%5,%6,%7}, {%8,%9}, {%0,%1,%2,%3};"
        : "+f"(c[0]), "+f"(c[1]), "+f"(c[2]), "+f"(c[3])
        : "r"(a0), "r"(a1), "r"(a2), "r"(a3), "r"(b0), "r"(b1));
}

// x = fdiff(z, axis) on the fly (0:W, 1:H, 2:D, 3:identity)
template<int MODE>
static __device__ __forceinline__ float getx(int d, int h, int w){
    if (d < 0 || d >= Dd || h < 0 || h >= Hh || w < 0 || w >= Ww) return 0.f;
    int idx = (d*Hh + h)*Ww + w;
    if (MODE == 0) return (w < Ww-1) ? g_z[idx+1]  - g_z[idx] : 0.f;
    if (MODE == 1) return (h < Hh-1) ? g_z[idx+Ww] - g_z[idx] : 0.f;
    if (MODE == 2) return (d < Dd-1) ? g_z[idx+HW] - g_z[idx] : 0.f;
    return g_z[idx];
}

// ---------------- init / colsum / z ---------------------------------------------
__global__ void k_init(const float* __restrict__ img, float* __restrict__ outp){
    int idx = blockIdx.x*256 + threadIdx.x;
    float v = img[idx];
    g_t[idx] = v;
    outp[idx] = v;
    g_p[idx] = 0.f; g_q[idx] = 0.f; g_s[idx] = 0.f;
}
__global__ void k_colsum(){
    int j = blockIdx.x*256 + threadIdx.x;
    float a0=0.f, a1=0.f, a2=0.f, a3=0.f;
    #pragma unroll
    for (int d = 0; d < Dd; d += 4){
        a0 += g_t[(d+0)*HW + j];
        a1 += g_t[(d+1)*HW + j];
        a2 += g_t[(d+2)*HW + j];
        a3 += g_t[(d+3)*HW + j];
    }
    g_sums[j] = (a0+a1)+(a2+a3);
}
__global__ void k_z(const float* __restrict__ sino){
    int idx = blockIdx.x*256 + threadIdx.x;
    int j = idx & (HW-1);
    g_z[idx] = g_t[idx] + (sino[j] - g_sums[j]) * (1.f/64.f);
}

// ================= conv1: 1 -> 16, fused fdiff input, relu, interleaved out ====
template<int MODE>
__global__ void __launch_bounds__(256) k_conv1(const float* __restrict__ w1,
                                               const float* __restrict__ b1){
    __shared__ float sx[2040];                            // 6 x 10 x 34 halo tile
    __shared__ __align__(16) unsigned long long swt[216]; // 27 k x 8 co-pairs
    const int tx = threadIdx.x, ty = threadIdx.y;
    const int tid = ty*32 + tx;
    const int w0 = blockIdx.x*32, h0 = blockIdx.y*8, d0 = blockIdx.z*4;

    if (tid < 216){
        int cp = tid & 7, k = tid >> 3;
        swt[tid] = pack2(w1[(2*cp)*27 + k], w1[(2*cp+1)*27 + k]);
    }
    for (int i = tid; i < 2040; i += 256){
        int xx = i % 34; int r = i / 34;
        int yy = r % 10; int dz = r / 10;
        sx[i] = getx<MODE>(d0-1+dz, h0-1+yy, w0-1+xx);
    }
    __syncthreads();

    unsigned long long acc[4][8];
    #pragma unroll
    for (int dz=0; dz<4; dz++)
        #pragma unroll
        for (int cp=0; cp<8; cp++) acc[dz][cp] = 0ull;

    const float* bx = sx + ty*34 + tx;
    #pragma unroll
    for (int kh=0; kh<3; kh++)
    #pragma unroll
    for (int kw=0; kw<3; kw++){
        unsigned long long x2[6];
        #pragma unroll
        for (int j=0; j<6; j++){
            float xv = bx[j*340 + kh*34 + kw];
            x2[j] = pack2(xv, xv);
        }
        #pragma unroll
        for (int kd=0; kd<3; kd++){
            const int k = (kd*3+kh)*3+kw;
            const ulonglong2* wp = reinterpret_cast<const ulonglong2*>(swt + k*8);
            #pragma unroll
            for (int jp=0; jp<4; jp++){
                ulonglong2 wv = wp[jp];
                #pragma unroll
                for (int dz=0; dz<4; dz++){
                    ffma2(acc[dz][2*jp],   x2[dz+kd], wv.x);
                    ffma2(acc[dz][2*jp+1], x2[dz+kd], wv.y);
                }
            }
        }
    }

    const int hh = h0+ty, ww = w0+tx;
    #pragma unroll
    for (int dz=0; dz<4; dz++){
        int pos = ((d0+dz)*Hh + hh)*Ww + ww;
        #pragma unroll
        for (int cp=0; cp<8; cp++){
            float lo, hi; unpack2(acc[dz][cp], lo, hi);
            float2 o;
            o.x = fmaxf(lo + b1[2*cp],   0.f);
            o.y = fmaxf(hi + b1[2*cp+1], 0.f);
            *reinterpret_cast<float2*>(&g_h1[pos*16 + 2*cp]) = o;
        }
    }
}

// ================= conv2: 16 -> 16 via mma.sync tf32 implicit GEMM =============
// CTA tile: 8(w) x 16(h) x 4(d) outputs, 16 co. GEMM per d-slice:
// D[M=128 = h*8+w][N=16] = sum over 9 taps (dd,dh), K=48 = dw*16+ci
// (x3 dw-replication staged in SMEM so taps are pure address offsets).
// A layout: [b = dhalo*18 + hhalo][kstep 0..5][w 0..7][c 0..3][half 0..1]
//   element (w, kappa): kappa = ks*8 + half*4 + c  -> (col c, col c+4) adjacent.
// B layout: fragment-major [tap][ks][ntile][lane][2 floats] (b0,b1 adjacent).
#define A_BYTES (108*1536)
#define B_OFF   A_BYTES                     // 165888
#define CV2_SMEM (B_OFF + 9*3072)           // 193536

__global__ void __launch_bounds__(256) k_conv2m(const float* __restrict__ w2,
                                                const float* __restrict__ b2){
    extern __shared__ char smem[];
    const int tid = threadIdx.x;
    const int wid = tid >> 5;
    const int lane = tid & 31;
    const int w0 = blockIdx.x*8, h0 = blockIdx.y*16, d0 = blockIdx.z*4;

    const uint32_t sbase  = smem_u32(smem);
    const uint32_t a_addr = sbase;
    const uint32_t b_addr = sbase + B_OFF;

    // ---- stage A: halo tile, x3 dw-replicated, frag-pair layout, tf32-cvt ----
    for (int i = tid; i < 10368; i += 256){
        int b  = i / 96;                 // 0..107 : dhalo*18 + hhalo
        int t  = i % 96;
        int ks = t >> 4;                 // 0..5
        int t2 = t & 15;
        int w  = t2 >> 1;                // 0..7
        int half = t2 & 1;
        int kb = ks*8 + half*4;          // kappa base, multiple of 4
        int dw = kb >> 4;
        int cib = kb & 15;
        int d = d0 - 1 + b/18;
        int h = h0 - 1 + b%18;
        int wg = w0 + w + dw - 1;
        float4 v = make_float4(0.f,0.f,0.f,0.f);
        if (d >= 0 && d < Dd && h >= 0 && h < Hh && wg >= 0 && wg < Ww)
            v = *reinterpret_cast<const float4*>(&g_h1[((d*Hh + h)*Ww + wg)*16 + cib]);
        char* dst = smem + b*1536 + ks*256 + w*32 + half*4;
        *reinterpret_cast<uint32_t*>(dst +  0) = f2tf32(v.x);
        *reinterpret_cast<uint32_t*>(dst +  8) = f2tf32(v.y);
        *reinterpret_cast<uint32_t*>(dst + 16) = f2tf32(v.z);
        *reinterpret_cast<uint32_t*>(dst + 24) = f2tf32(v.w);
    }
    // ---- stage B: fragment-major weights, tf32-cvt ----
    for (int i = tid; i < 3456; i += 256){
        int l   = i & 31;
        int nt  = (i >> 5) & 1;
        int ks  = (i >> 6) % 6;
        int tap = i / 384;
        int dd = tap/3, dh = tap%3;
        int k0 = l & 3, n = l >> 2;
        int co = nt*8 + n;
        int ka = ks*8 + k0;              // b0 kappa
        int kb = ka + 4;                 // b1 kappa
        float v0 = w2[(co*16 + (ka & 15))*27 + dd*9 + dh*3 + (ka >> 4)];
        float v1 = w2[(co*16 + (kb & 15))*27 + dd*9 + dh*3 + (kb >> 4)];
        char* dst = smem + B_OFF + tap*3072 + ks*512 + nt*256 + l*8;
        *reinterpret_cast<uint32_t*>(dst + 0) = f2tf32(v0);
        *reinterpret_cast<uint32_t*>(dst + 4) = f2tf32(v1);
    }
    __syncthreads();

    // ---- mainloop: each warp = one 16-row M-tile (h rows 2*wid, 2*wid+1) ----
    const int c = lane & 3, r = lane >> 2;
    float acc[4][8];                     // [d-slice][ntile*4 + frag]
    #pragma unroll
    for (int s=0; s<4; s++)
        #pragma unroll
        for (int j=0; j<8; j++) acc[s][j] = 0.f;

    #pragma unroll 1
    for (int tap = 0; tap < 9; tap++){
        int dd = tap/3, dh = tap%3;
        uint32_t arow = a_addr + (uint32_t)(2*wid + dh)*1536u + (uint32_t)r*32u + (uint32_t)c*8u
                               + (uint32_t)dd*27648u;
        uint32_t bb = b_addr + (uint32_t)tap*3072u + (uint32_t)lane*8u;
        #pragma unroll
        for (int ks = 0; ks < 6; ks++){
            uint32_t b00, b01, b10, b11;
            lds_v2(bb + ks*512,        b00, b01);
            lds_v2(bb + ks*512 + 256,  b10, b11);
            #pragma unroll
            for (int s = 0; s < 4; s++){
                uint32_t aa = arow + (uint32_t)s*27648u + (uint32_t)ks*256u;
                uint32_t a0, a2, a1, a3;
                lds_v2(aa,        a0, a2);
                lds_v2(aa + 1536, a1, a3);
                mma_tf32(&acc[s][0], a0, a1, a2, a3, b00, b01);
                mma_tf32(&acc[s][4], a0, a1, a2, a3, b10, b11);
            }
        }
    }

    // ---- epilogue: bias + relu, float2 stores to interleaved g_h2 ----
    #pragma unroll
    for (int nt = 0; nt < 2; nt++){
        int col = nt*8 + 2*c;
        float bl = b2[col], bh = b2[col+1];
        #pragma unroll
        for (int s = 0; s < 4; s++){
            int d = d0 + s;
            int hA = h0 + 2*wid;
            int wA = w0 + r;
            float2 o0, o1;
            o0.x = fmaxf(acc[s][nt*4+0] + bl, 0.f);
            o0.y = fmaxf(acc[s][nt*4+1] + bh, 0.f);
            o1.x = fmaxf(acc[s][nt*4+2] + bl, 0.f);
            o1.y = fmaxf(acc[s][nt*4+3] + bh, 0.f);
            *reinterpret_cast<float2*>(&g_h2[((d*Hh + hA  )*Ww + wA)*16 + col]) = o0;
            *reinterpret_cast<float2*>(&g_h2[((d*Hh + hA+1)*Ww + wA)*16 + col]) = o1;
        }
    }
}

// ================= conv3: 16 -> 1, interleaved input, fused updates ============
template<int A>
__global__ void __launch_bounds__(256) k_conv3(const float* __restrict__ w3,
                                               const float* __restrict__ b3,
                                               const float* __restrict__ eta_arr,
                                               int c){
    __shared__ float sx[4*2040];
    __shared__ float swt[108];
    const int tx = threadIdx.x, ty = threadIdx.y;
    const int tid = ty*32 + tx;
    const int w0 = blockIdx.x*32, h0 = blockIdx.y*8, d0 = blockIdx.z*4;

    unsigned long long acc2[2] = {0ull, 0ull};

    for (int cc = 0; cc < 4; cc++){
        __syncthreads();
        if (tid < 108){
            int k = tid % 27, ci4 = tid / 27;
            swt[tid] = w3[(cc*4 + ci4)*27 + k];
        }
        for (int i = tid; i < 2040; i += 256){
            int xx = i % 34; int r = i / 34;
            int yy = r % 10; int dz = r / 10;
            int d = d0-1+dz, h = h0-1+yy, w = w0-1+xx;
            float4 v = make_float4(0.f,0.f,0.f,0.f);
            if (d >= 0 && d < Dd && h >= 0 && h < Hh && w >= 0 && w < Ww)
                v = *reinterpret_cast<const float4*>(&g_h2[((d*Hh + h)*Ww + w)*16 + cc*4]);
            sx[0*2040 + i] = v.x;
            sx[1*2040 + i] = v.y;
            sx[2*2040 + i] = v.z;
            sx[3*2040 + i] = v.w;
        }
        __syncthreads();

        #pragma unroll 1
        for (int ci4 = 0; ci4 < 4; ci4++){
            const float* bx = sx + ci4*2040 + ty*34 + tx;
            const float* bw = swt + ci4*27;
            #pragma unroll
            for (int kh=0; kh<3; kh++)
            #pragma unroll
            for (int kw=0; kw<3; kw++){
                float xv[6];
                #pragma unroll
                for (int j=0; j<6; j++) xv[j] = bx[j*340 + kh*34 + kw];
                unsigned long long xp[5];
                #pragma unroll
                for (int j=0; j<5; j++) xp[j] = pack2(xv[j], xv[j+1]);
                #pragma unroll
                for (int kd=0; kd<3; kd++){
                    float wv = bw[(kd*3+kh)*3+kw];
                    unsigned long long wv2 = pack2(wv, wv);
                    ffma2(acc2[0], xp[kd],   wv2);
                    ffma2(acc2[1], xp[kd+2], wv2);
                }
            }
        }
    }

    float accd[4];
    unpack2(acc2[0], accd[0], accd[1]);
    unpack2(acc2[1], accd[2], accd[3]);

    float* tgt        = (A==0) ? g_p : (A==1) ? g_q : (A==2) ? g_s : g_zp;
    const float* base = (A==3) ? g_t : tgt;
    const float eta = eta_arr[c];
    const float b3v = b3[0];
    const int hh = h0+ty, ww = w0+tx;
    #pragma unroll
    for (int dz=0; dz<4; dz++){
        int d = d0+dz;
        int idx = (d*Hh + hh)*Ww + ww;
        float nnew = getx<A>(d, hh, ww) + accd[dz] + b3v;
        tgt[idx] = (1.f + eta)*base[idx] - eta*nnew;
    }
}

// ---------------- update: t = fdT_w(p)+fdT_h(q)+fdT_d(s)+z', write out --------
__global__ void k_update(float* __restrict__ outp){
    int idx = blockIdx.x*256 + threadIdx.x;
    int w = idx & (Ww-1);
    int h = (idx >> 7) & (Hh-1);
    int d = idx >> 14;
    float fa = (w==Ww-1) ? g_p[idx-1]  : ((w>0 ? g_p[idx-1]  : 0.f) - g_p[idx]);
    float fb = (h==Hh-1) ? g_q[idx-Ww] : ((h>0 ? g_q[idx-Ww] : 0.f) - g_q[idx]);
    float fc = (d==Dd-1) ? g_s[idx-HW] : ((d>0 ? g_s[idx-HW] : 0.f) - g_s[idx]);
    float tn = fa + fb + fc + g_zp[idx];
    g_t[idx] = tn;
    outp[idx] = tn;
}

// ---------------- launcher -----------------------------------------------------
extern "C" void kernel_launch(void* const* d_in, const int* in_sizes, int n_in,
                              void* d_out, int out_size){
    (void)in_sizes; (void)n_in; (void)out_size;
    const float* img  = (const float*)d_in[0];
    const float* sino = (const float*)d_in[1];
    const float* w1   = (const float*)d_in[2];
    const float* b1   = (const float*)d_in[3];
    const float* w2   = (const float*)d_in[4];
    const float* b2   = (const float*)d_in[5];
    const float* w3   = (const float*)d_in[6];
    const float* b3   = (const float*)d_in[7];
    const float* ntx  = (const float*)d_in[8];
    const float* nty  = (const float*)d_in[9];
    const float* ntz  = (const float*)d_in[10];
    const float* nt   = (const float*)d_in[11];
    float* out = (float*)d_out;

    cudaFuncSetAttribute(k_conv2m, cudaFuncAttributeMaxDynamicSharedMemorySize, CV2_SMEM);

    dim3 cg(4, 16, 16), cb(32, 8, 1);
    dim3 g2(16, 8, 16);                 // w/8, h/16, d/4
    k_init<<<NN/256, 256>>>(img, out);
    for (int c = 0; c < 3; c++){
        k_colsum<<<HW/256, 256>>>();
        k_z<<<NN/256, 256>>>(sino);

        k_conv1<0><<<cg, cb>>>(w1 + 0*432, b1 + 0*16);
        k_conv2m<<<g2, 256, CV2_SMEM>>>(w2 + 0*6912, b2 + 0*16);
        k_conv3<0><<<cg, cb>>>(w3 + 0*432, b3 + 0, ntx, c);

        k_conv1<1><<<cg, cb>>>(w1 + 1*432, b1 + 1*16);
        k_conv2m<<<g2, 256, CV2_SMEM>>>(w2 + 1*6912, b2 + 1*16);
        k_conv3<1><<<cg, cb>>>(w3 + 1*432, b3 + 1, nty, c);

        k_conv1<2><<<cg, cb>>>(w1 + 2*432, b1 + 2*16);
        k_conv2m<<<g2, 256, CV2_SMEM>>>(w2 + 2*6912, b2 + 2*16);
        k_conv3<2><<<cg, cb>>>(w3 + 2*432, b3 + 2, ntz, c);

        k_conv1<3><<<cg, cb>>>(w1 + 3*432, b1 + 3*16);
        k_conv2m<<<g2, 256, CV2_SMEM>>>(w2 + 3*6912, b2 + 3*16);
        k_conv3<3><<<cg, cb>>>(w3 + 3*432, b3 + 3, nt, c);

        k_update<<<NN/256, 256>>>(out + (c+1)*NN);
    }
}

// round 6
// speedup vs baseline: 2.6721x; 1.3453x over previous
#include <cuda_runtime.h>
#include <cstdint>

#define Dd 64
#define Hh 128
#define Ww 128
#define HW (Hh*Ww)
#define NN (Dd*Hh*Ww)

// ---------------- scratch (device globals: alloc-free, capture-safe) ----------
__device__ float g_t[NN];
__device__ float g_z[NN];
__device__ float g_p[NN];
__device__ float g_q[NN];
__device__ float g_s[NN];
__device__ float g_zp[NN];
__device__ float g_sums[HW];
__device__ float g_h1[16*NN];   // channel-interleaved: [pos][16 ci]
__device__ float g_h2[16*NN];   // PLANAR: [ci][pos]

// ---------------- packed f32x2 helpers -----------------------------------------
static __device__ __forceinline__ unsigned long long pack2(float lo, float hi){
    unsigned long long r;
    asm("mov.b64 %0, {%1,%2};" : "=l"(r) : "f"(lo), "f"(hi));
    return r;
}
static __device__ __forceinline__ void unpack2(unsigned long long v, float &lo, float &hi){
    asm("mov.b64 {%0,%1}, %2;" : "=f"(lo), "=f"(hi) : "l"(v));
}
static __device__ __forceinline__ void ffma2(unsigned long long &d, unsigned long long a, unsigned long long b){
    asm("fma.rn.f32x2 %0, %1, %2, %0;" : "+l"(d) : "l"(a), "l"(b));
}

// ---------------- mma.sync helpers (family-safe PTX, sm_80+) --------------------
static __device__ __forceinline__ uint32_t smem_u32(const void* p){
    uint32_t a;
    asm("{ .reg .u64 t; cvta.to.shared.u64 t, %1; cvt.u32.u64 %0, t; }" : "=r"(a) : "l"(p));
    return a;
}
static __device__ __forceinline__ uint32_t f2tf32(float x){
    uint32_t r;
    asm("cvt.rna.tf32.f32 %0, %1;" : "=r"(r) : "f"(x));
    return r;
}
static __device__ __forceinline__ void lds_v2(uint32_t addr, uint32_t &x, uint32_t &y){
    asm volatile("ld.shared.v2.u32 {%0,%1}, [%2];" : "=r"(x), "=r"(y) : "r"(addr));
}
static __device__ __forceinline__ void mma_tf32(float* c, uint32_t a0, uint32_t a1,
                                                uint32_t a2, uint32_t a3,
                                                uint32_t b0, uint32_t b1){
    asm volatile(
        "mma.sync.aligned.m16n8k8.row.col.f32.tf32.tf32.f32 "
        "{%0,%1,%2,%3}, {%4,%5,%6,%7}, {%8,%9}, {%0,%1,%2,%3};"
        : "+f"(c[0]), "+f"(c[1]), "+f"(c[2]), "+f"(c[3])
        : "r"(a0), "r"(a1), "r"(a2), "r"(a3), "r"(b0), "r"(b1));
}

// x = fdiff(z, axis) on the fly (0:W, 1:H, 2:D, 3:identity)
template<int MODE>
static __device__ __forceinline__ float getx(int d, int h, int w){
    if (d < 0 || d >= Dd || h < 0 || h >= Hh || w < 0 || w >= Ww) return 0.f;
    int idx = (d*Hh + h)*Ww + w;
    if (MODE == 0) return (w < Ww-1) ? g_z[idx+1]  - g_z[idx] : 0.f;
    if (MODE == 1) return (h < Hh-1) ? g_z[idx+Ww] - g_z[idx] : 0.f;
    if (MODE == 2) return (d < Dd-1) ? g_z[idx+HW] - g_z[idx] : 0.f;
    return g_z[idx];
}

// ---------------- init / colsum / z ---------------------------------------------
__global__ void k_init(const float* __restrict__ img, float* __restrict__ outp){
    int idx = blockIdx.x*256 + threadIdx.x;
    float v = img[idx];
    g_t[idx] = v;
    outp[idx] = v;
    g_p[idx] = 0.f; g_q[idx] = 0.f; g_s[idx] = 0.f;
}
__global__ void k_colsum(){
    int j = blockIdx.x*256 + threadIdx.x;
    float a0=0.f, a1=0.f, a2=0.f, a3=0.f;
    #pragma unroll
    for (int d = 0; d < Dd; d += 4){
        a0 += g_t[(d+0)*HW + j];
        a1 += g_t[(d+1)*HW + j];
        a2 += g_t[(d+2)*HW + j];
        a3 += g_t[(d+3)*HW + j];
    }
    g_sums[j] = (a0+a1)+(a2+a3);
}
__global__ void k_z(const float* __restrict__ sino){
    int idx = blockIdx.x*256 + threadIdx.x;
    int j = idx & (HW-1);
    g_z[idx] = g_t[idx] + (sino[j] - g_sums[j]) * (1.f/64.f);
}

// ================= conv1: 1 -> 16, fused fdiff, relu, interleaved out =========
// Output staged through SMEM so gmem writes are coalesced float4.
template<int MODE>
__global__ void __launch_bounds__(256) k_conv1(const float* __restrict__ w1,
                                               const float* __restrict__ b1){
    __shared__ float sx[2040];                            // 6 x 10 x 34 halo tile
    __shared__ __align__(16) unsigned long long swt[216]; // 27 k x 8 co-pairs
    __shared__ __align__(16) float sb[256*20];            // transpose buf (80B rows)
    const int tx = threadIdx.x, ty = threadIdx.y;
    const int tid = ty*32 + tx;
    const int w0 = blockIdx.x*32, h0 = blockIdx.y*8, d0 = blockIdx.z*4;

    if (tid < 216){
        int cp = tid & 7, k = tid >> 3;
        swt[tid] = pack2(w1[(2*cp)*27 + k], w1[(2*cp+1)*27 + k]);
    }
    for (int i = tid; i < 2040; i += 256){
        int xx = i % 34; int r = i / 34;
        int yy = r % 10; int dz = r / 10;
        sx[i] = getx<MODE>(d0-1+dz, h0-1+yy, w0-1+xx);
    }
    __syncthreads();

    unsigned long long acc[4][8];
    #pragma unroll
    for (int dz=0; dz<4; dz++)
        #pragma unroll
        for (int cp=0; cp<8; cp++) acc[dz][cp] = 0ull;

    const float* bx = sx + ty*34 + tx;
    #pragma unroll
    for (int kh=0; kh<3; kh++)
    #pragma unroll
    for (int kw=0; kw<3; kw++){
        unsigned long long x2[6];
        #pragma unroll
        for (int j=0; j<6; j++){
            float xv = bx[j*340 + kh*34 + kw];
            x2[j] = pack2(xv, xv);
        }
        #pragma unroll
        for (int kd=0; kd<3; kd++){
            const int k = (kd*3+kh)*3+kw;
            const ulonglong2* wp = reinterpret_cast<const ulonglong2*>(swt + k*8);
            #pragma unroll
            for (int jp=0; jp<4; jp++){
                ulonglong2 wv = wp[jp];
                #pragma unroll
                for (int dz=0; dz<4; dz++){
                    ffma2(acc[dz][2*jp],   x2[dz+kd], wv.x);
                    ffma2(acc[dz][2*jp+1], x2[dz+kd], wv.y);
                }
            }
        }
    }

    float bl[8], bh[8];
    #pragma unroll
    for (int cp=0; cp<8; cp++){ bl[cp] = b1[2*cp]; bh[cp] = b1[2*cp+1]; }

    #pragma unroll 1
    for (int dz=0; dz<4; dz++){
        __syncthreads();                 // protect sb reuse across dz
        #pragma unroll
        for (int cp=0; cp<8; cp++){
            float lo, hi; unpack2(acc[dz][cp], lo, hi);
            float2 o;
            o.x = fmaxf(lo + bl[cp], 0.f);
            o.y = fmaxf(hi + bh[cp], 0.f);
            *reinterpret_cast<float2*>(sb + tid*20 + cp*2) = o;
        }
        __syncthreads();
        for (int j = tid; j < 1024; j += 256){
            int p = j >> 2, cc = j & 3;
            float4 v = *reinterpret_cast<float4*>(sb + p*20 + cc*4);
            int h = p >> 5, w = p & 31;
            *reinterpret_cast<float4*>(
                &g_h1[(((d0+dz)*Hh + h0+h)*Ww + w0+w)*16 + cc*4]) = v;
        }
    }
}

// ================= conv2: 16 -> 16 via mma.sync tf32 implicit GEMM =============
// CTA tile: 8(w) x 16(h) x 4(d), 16 co. D[M=128][N=16], 27 taps (dd,dh,dw), K=16.
// A SMEM (unreplicated, w-halo): block b = dhalo*18 + hhalo (108 blocks, 640B):
//   [ks 2][w 10][c 4][half 2] x 4B; element (w, ci): ks=ci>>3, half=(ci>>2)&1, c=ci&3.
// dw tap = +dw*32B, dh = +dh*640B, dd = +dd*11520B in block address.
// B SMEM: [tap 27][ks 2][nt 2][lane 32][pair 2] = 27648B.
#define A_BYTES (108*640)                  // 69120
#define B_OFF   A_BYTES
#define CV2_SMEM (B_OFF + 27*1024)         // 96768

__global__ void __launch_bounds__(256) k_conv2m(const float* __restrict__ w2,
                                                const float* __restrict__ b2){
    extern __shared__ char smem[];
    const int tid = threadIdx.x;
    const int wid = tid >> 5;
    const int lane = tid & 31;
    const int w0 = blockIdx.x*8, h0 = blockIdx.y*16, d0 = blockIdx.z*4;

    const uint32_t sbase  = smem_u32(smem);
    const uint32_t a_addr = sbase;
    const uint32_t b_addr = sbase + B_OFF;

    // ---- stage A: coalesced float4 reads of interleaved h1, tf32-cvt ----
    for (int i = tid; i < 4320; i += 256){
        int c4 = i & 3;
        int w  = (i >> 2) % 10;
        int b  = i / 40;
        int d = d0 - 1 + b/18;
        int h = h0 - 1 + b%18;
        int wg = w0 - 1 + w;
        float4 v = make_float4(0.f,0.f,0.f,0.f);
        if (d >= 0 && d < Dd && h >= 0 && h < Hh && wg >= 0 && wg < Ww)
            v = *reinterpret_cast<const float4*>(&g_h1[((d*Hh + h)*Ww + wg)*16 + c4*4]);
        char* dst = smem + b*640 + (c4>>1)*320 + w*32 + (c4&1)*4;
        *reinterpret_cast<uint32_t*>(dst +  0) = f2tf32(v.x);
        *reinterpret_cast<uint32_t*>(dst +  8) = f2tf32(v.y);
        *reinterpret_cast<uint32_t*>(dst + 16) = f2tf32(v.z);
        *reinterpret_cast<uint32_t*>(dst + 24) = f2tf32(v.w);
    }
    // ---- stage B: fragment-major weights, tf32-cvt ----
    for (int i = tid; i < 3456; i += 256){
        int l   = i & 31;
        int nt  = (i >> 5) & 1;
        int ks  = (i >> 6) & 1;
        int tap = i >> 7;                 // 0..26 = dd*9 + dh*3 + dw
        int k0 = l & 3, n = l >> 2;
        int co = nt*8 + n;
        int ca = ks*8 + k0;
        float v0 = w2[(co*16 + ca  )*27 + tap];
        float v1 = w2[(co*16 + ca+4)*27 + tap];
        char* dst = smem + B_OFF + tap*1024 + ks*512 + nt*256 + l*8;
        *reinterpret_cast<uint32_t*>(dst + 0) = f2tf32(v0);
        *reinterpret_cast<uint32_t*>(dst + 4) = f2tf32(v1);
    }
    __syncthreads();

    // ---- mainloop ----
    const int c = lane & 3, r = lane >> 2;
    float acc[4][8];
    #pragma unroll
    for (int s=0; s<4; s++)
        #pragma unroll
        for (int j=0; j<8; j++) acc[s][j] = 0.f;

    const uint32_t a_row = a_addr + (uint32_t)(2*wid)*640u + (uint32_t)r*32u + (uint32_t)c*8u;
    const uint32_t b_row = b_addr + (uint32_t)lane*8u;

    #pragma unroll 1
    for (int dh = 0; dh < 3; dh++){
        #pragma unroll
        for (int dw = 0; dw < 3; dw++){
            uint32_t bfr[3][2][2][2];
            #pragma unroll
            for (int dd=0; dd<3; dd++)
                #pragma unroll
                for (int ks=0; ks<2; ks++)
                    #pragma unroll
                    for (int nt=0; nt<2; nt++)
                        lds_v2(b_row + (uint32_t)(dd*9 + dh*3 + dw)*1024u
                                      + ks*512u + nt*256u,
                               bfr[dd][ks][nt][0], bfr[dd][ks][nt][1]);
            #pragma unroll
            for (int ks=0; ks<2; ks++){
                #pragma unroll
                for (int dblk=0; dblk<6; dblk++){
                    uint32_t aa = a_row + (uint32_t)dh*640u + (uint32_t)dblk*11520u
                                        + (uint32_t)ks*320u + (uint32_t)dw*32u;
                    uint32_t a0,a2,a1,a3;
                    lds_v2(aa,        a0, a2);
                    lds_v2(aa + 640u, a1, a3);
                    #pragma unroll
                    for (int dd=0; dd<3; dd++){
                        const int s = dblk - dd;
                        if (s >= 0 && s < 4){
                            mma_tf32(&acc[s][0], a0,a1,a2,a3,
                                     bfr[dd][ks][0][0], bfr[dd][ks][0][1]);
                            mma_tf32(&acc[s][4], a0,a1,a2,a3,
                                     bfr[dd][ks][1][0], bfr[dd][ks][1][1]);
                        }
                    }
                }
            }
        }
    }

    // ---- epilogue: bias + relu, planar h2 stores ----
    #pragma unroll
    for (int nt = 0; nt < 2; nt++){
        int col = nt*8 + 2*c;
        float blv = b2[col], bhv = b2[col+1];
        #pragma unroll
        for (int s = 0; s < 4; s++){
            int base0 = ((d0+s)*Hh + h0 + 2*wid)*Ww + w0 + r;
            g_h2[ col   *NN + base0]    = fmaxf(acc[s][nt*4+0] + blv, 0.f);
            g_h2[(col+1)*NN + base0]    = fmaxf(acc[s][nt*4+1] + bhv, 0.f);
            g_h2[ col   *NN + base0+Ww] = fmaxf(acc[s][nt*4+2] + blv, 0.f);
            g_h2[(col+1)*NN + base0+Ww] = fmaxf(acc[s][nt*4+3] + bhv, 0.f);
        }
    }
}

// ================= conv3: 16 -> 1, planar input, fused updates =================
template<int A>
__global__ void __launch_bounds__(256) k_conv3(const float* __restrict__ w3,
                                               const float* __restrict__ b3,
                                               const float* __restrict__ eta_arr,
                                               int c){
    __shared__ float sx[4*2040];
    __shared__ float swt[108];
    const int tx = threadIdx.x, ty = threadIdx.y;
    const int tid = ty*32 + tx;
    const int w0 = blockIdx.x*32, h0 = blockIdx.y*8, d0 = blockIdx.z*4;

    unsigned long long acc2[2] = {0ull, 0ull};

    for (int cc = 0; cc < 4; cc++){
        __syncthreads();
        if (tid < 108){
            int k = tid % 27, ci4 = tid / 27;
            swt[tid] = w3[(cc*4 + ci4)*27 + k];
        }
        for (int i = tid; i < 8160; i += 256){
            int xx = i % 34; int r = i / 34;
            int yy = r % 10; int r2 = r / 10;
            int dz = r2 % 6; int ci4 = r2 / 6;
            int d = d0-1+dz, h = h0-1+yy, w = w0-1+xx;
            float v = 0.f;
            if (d >= 0 && d < Dd && h >= 0 && h < Hh && w >= 0 && w < Ww)
                v = g_h2[(cc*4 + ci4)*NN + (d*Hh + h)*Ww + w];
            sx[i] = v;
        }
        __syncthreads();

        #pragma unroll 1
        for (int ci4 = 0; ci4 < 4; ci4++){
            const float* bx = sx + ci4*2040 + ty*34 + tx;
            const float* bw = swt + ci4*27;
            #pragma unroll
            for (int kh=0; kh<3; kh++)
            #pragma unroll
            for (int kw=0; kw<3; kw++){
                float xv[6];
                #pragma unroll
                for (int j=0; j<6; j++) xv[j] = bx[j*340 + kh*34 + kw];
                unsigned long long xp[5];
                #pragma unroll
                for (int j=0; j<5; j++) xp[j] = pack2(xv[j], xv[j+1]);
                #pragma unroll
                for (int kd=0; kd<3; kd++){
                    float wv = bw[(kd*3+kh)*3+kw];
                    unsigned long long wv2 = pack2(wv, wv);
                    ffma2(acc2[0], xp[kd],   wv2);
                    ffma2(acc2[1], xp[kd+2], wv2);
                }
            }
        }
    }

    float accd[4];
    unpack2(acc2[0], accd[0], accd[1]);
    unpack2(acc2[1], accd[2], accd[3]);

    float* tgt        = (A==0) ? g_p : (A==1) ? g_q : (A==2) ? g_s : g_zp;
    const float* base = (A==3) ? g_t : tgt;
    const float eta = eta_arr[c];
    const float b3v = b3[0];
    const int hh = h0+ty, ww = w0+tx;
    #pragma unroll
    for (int dz=0; dz<4; dz++){
        int d = d0+dz;
        int idx = (d*Hh + hh)*Ww + ww;
        float nnew = getx<A>(d, hh, ww) + accd[dz] + b3v;
        tgt[idx] = (1.f + eta)*base[idx] - eta*nnew;
    }
}

// ---------------- update: t = fdT_w(p)+fdT_h(q)+fdT_d(s)+z', write out --------
__global__ void k_update(float* __restrict__ outp){
    int idx = blockIdx.x*256 + threadIdx.x;
    int w = idx & (Ww-1);
    int h = (idx >> 7) & (Hh-1);
    int d = idx >> 14;
    float fa = (w==Ww-1) ? g_p[idx-1]  : ((w>0 ? g_p[idx-1]  : 0.f) - g_p[idx]);
    float fb = (h==Hh-1) ? g_q[idx-Ww] : ((h>0 ? g_q[idx-Ww] : 0.f) - g_q[idx]);
    float fc = (d==Dd-1) ? g_s[idx-HW] : ((d>0 ? g_s[idx-HW] : 0.f) - g_s[idx]);
    float tn = fa + fb + fc + g_zp[idx];
    g_t[idx] = tn;
    outp[idx] = tn;
}

// ---------------- launcher -----------------------------------------------------
extern "C" void kernel_launch(void* const* d_in, const int* in_sizes, int n_in,
                              void* d_out, int out_size){
    (void)in_sizes; (void)n_in; (void)out_size;
    const float* img  = (const float*)d_in[0];
    const float* sino = (const float*)d_in[1];
    const float* w1   = (const float*)d_in[2];
    const float* b1   = (const float*)d_in[3];
    const float* w2   = (const float*)d_in[4];
    const float* b2   = (const float*)d_in[5];
    const float* w3   = (const float*)d_in[6];
    const float* b3   = (const float*)d_in[7];
    const float* ntx  = (const float*)d_in[8];
    const float* nty  = (const float*)d_in[9];
    const float* ntz  = (const float*)d_in[10];
    const float* nt   = (const float*)d_in[11];
    float* out = (float*)d_out;

    cudaFuncSetAttribute(k_conv2m, cudaFuncAttributeMaxDynamicSharedMemorySize, CV2_SMEM);

    dim3 cg(4, 16, 16), cb(32, 8, 1);
    dim3 g2(16, 8, 16);                 // w/8, h/16, d/4
    k_init<<<NN/256, 256>>>(img, out);
    for (int c = 0; c < 3; c++){
        k_colsum<<<HW/256, 256>>>();
        k_z<<<NN/256, 256>>>(sino);

        k_conv1<0><<<cg, cb>>>(w1 + 0*432, b1 + 0*16);
        k_conv2m<<<g2, 256, CV2_SMEM>>>(w2 + 0*6912, b2 + 0*16);
        k_conv3<0><<<cg, cb>>>(w3 + 0*432, b3 + 0, ntx, c);

        k_conv1<1><<<cg, cb>>>(w1 + 1*432, b1 + 1*16);
        k_conv2m<<<g2, 256, CV2_SMEM>>>(w2 + 1*6912, b2 + 1*16);
        k_conv3<1><<<cg, cb>>>(w3 + 1*432, b3 + 1, nty, c);

        k_conv1<2><<<cg, cb>>>(w1 + 2*432, b1 + 2*16);
        k_conv2m<<<g2, 256, CV2_SMEM>>>(w2 + 2*6912, b2 + 2*16);
        k_conv3<2><<<cg, cb>>>(w3 + 2*432, b3 + 2, ntz, c);

        k_conv1<3><<<cg, cb>>>(w1 + 3*432, b1 + 3*16);
        k_conv2m<<<g2, 256, CV2_SMEM>>>(w2 + 3*6912, b2 + 3*16);
        k_conv3<3><<<cg, cb>>>(w3 + 3*432, b3 + 3, nt, c);

        k_update<<<NN/256, 256>>>(out + (c+1)*NN);
    }
}

// round 8
// speedup vs baseline: 5.6762x; 2.1242x over previous
#include <cuda_runtime.h>
#include <cstdint>

#define Dd 64
#define Hh 128
#define Ww 128
#define HW (Hh*Ww)
#define NN (Dd*Hh*Ww)

// ---------------- scratch (device globals: alloc-free, capture-safe) ----------
__device__ float g_t[NN];
__device__ float g_z[NN];
__device__ float g_p[NN];
__device__ float g_q[NN];
__device__ float g_s[NN];
__device__ float g_zp[NN];
__device__ float g_sums[HW];
// bf16 intermediates, channel-interleaved + ci-pair permuted:
//   u32 index = pos*8 + (j&3)*2 + (j>>2), where j = ci>>1 (pair index)
__device__ uint32_t g_h1b[8*NN];
__device__ uint32_t g_h2b[8*NN];

// ---------------- packed f32x2 helpers -----------------------------------------
static __device__ __forceinline__ unsigned long long pack2(float lo, float hi){
    unsigned long long r;
    asm("mov.b64 %0, {%1,%2};" : "=l"(r) : "f"(lo), "f"(hi));
    return r;
}
static __device__ __forceinline__ void unpack2(unsigned long long v, float &lo, float &hi){
    asm("mov.b64 {%0,%1}, %2;" : "=f"(lo), "=f"(hi) : "l"(v));
}
static __device__ __forceinline__ void ffma2(unsigned long long &d, unsigned long long a, unsigned long long b){
    asm("fma.rn.f32x2 %0, %1, %2, %0;" : "+l"(d) : "l"(a), "l"(b));
}

// ---------------- bf16 / mma.sync helpers (family-safe PTX) ---------------------
static __device__ __forceinline__ uint32_t smem_u32(const void* p){
    uint32_t a;
    asm("{ .reg .u64 t; cvta.to.shared.u64 t, %1; cvt.u32.u64 %0, t; }" : "=r"(a) : "l"(p));
    return a;
}
static __device__ __forceinline__ uint32_t bf16x2(float lo, float hi){
    uint32_t r;
    asm("cvt.rn.bf16x2.f32 %0, %1, %2;" : "=r"(r) : "f"(hi), "f"(lo));
    return r;
}
static __device__ __forceinline__ void lds_v2(uint32_t addr, uint32_t &x, uint32_t &y){
    asm volatile("ld.shared.v2.u32 {%0,%1}, [%2];" : "=r"(x), "=r"(y) : "r"(addr));
}
static __device__ __forceinline__ void mma_bf16(float* c, uint32_t a0, uint32_t a1,
                                                uint32_t a2, uint32_t a3,
                                                uint32_t b0, uint32_t b1){
    asm volatile(
        "mma.sync.aligned.m16n8k16.row.col.f32.bf16.bf16.f32 "
        "{%0,%1,%2,%3}, {%4,%5,%6,%7}, {%8,%9}, {%0,%1,%2,%3};"
        : "+f"(c[0]), "+f"(c[1]), "+f"(c[2]), "+f"(c[3])
        : "r"(a0), "r"(a1), "r"(a2), "r"(a3), "r"(b0), "r"(b1));
}

// x = fdiff(z, axis) on the fly (0:W, 1:H, 2:D, 3:identity)
template<int MODE>
static __device__ __forceinline__ float getx(int d, int h, int w){
    if (d < 0 || d >= Dd || h < 0 || h >= Hh || w < 0 || w >= Ww) return 0.f;
    int idx = (d*Hh + h)*Ww + w;
    if (MODE == 0) return (w < Ww-1) ? g_z[idx+1]  - g_z[idx] : 0.f;
    if (MODE == 1) return (h < Hh-1) ? g_z[idx+Ww] - g_z[idx] : 0.f;
    if (MODE == 2) return (d < Dd-1) ? g_z[idx+HW] - g_z[idx] : 0.f;
    return g_z[idx];
}

// ---------------- init / colsum / z ---------------------------------------------
__global__ void k_init(const float* __restrict__ img, float* __restrict__ outp){
    int idx = blockIdx.x*256 + threadIdx.x;
    float v = img[idx];
    g_t[idx] = v;
    outp[idx] = v;
    g_p[idx] = 0.f; g_q[idx] = 0.f; g_s[idx] = 0.f;
}
__global__ void k_colsum(){
    int j = blockIdx.x*256 + threadIdx.x;
    float a0=0.f, a1=0.f, a2=0.f, a3=0.f;
    #pragma unroll
    for (int d = 0; d < Dd; d += 4){
        a0 += g_t[(d+0)*HW + j];
        a1 += g_t[(d+1)*HW + j];
        a2 += g_t[(d+2)*HW + j];
        a3 += g_t[(d+3)*HW + j];
    }
    g_sums[j] = (a0+a1)+(a2+a3);
}
__global__ void k_z(const float* __restrict__ sino){
    int idx = blockIdx.x*256 + threadIdx.x;
    int j = idx & (HW-1);
    g_z[idx] = g_t[idx] + (sino[j] - g_sums[j]) * (1.f/64.f);
}

// ================= conv1: 1 -> 16, fused fdiff, relu, bf16 permuted out =======
template<int MODE>
__global__ void __launch_bounds__(256) k_conv1(const float* __restrict__ w1,
                                               const float* __restrict__ b1){
    __shared__ float sx[2040];                            // 6 x 10 x 34 halo tile
    __shared__ __align__(16) unsigned long long swt[216]; // 27 k x 8 co-pairs
    __shared__ uint32_t sb[2048];                          // 256 pos x 8 bf16x2
    const int tx = threadIdx.x, ty = threadIdx.y;
    const int tid = ty*32 + tx;
    const int w0 = blockIdx.x*32, h0 = blockIdx.y*8, d0 = blockIdx.z*4;

    if (tid < 216){
        int cp = tid & 7, k = tid >> 3;
        swt[tid] = pack2(w1[(2*cp)*27 + k], w1[(2*cp+1)*27 + k]);
    }
    for (int i = tid; i < 2040; i += 256){
        int xx = i % 34; int r = i / 34;
        int yy = r % 10; int dz = r / 10;
        sx[i] = getx<MODE>(d0-1+dz, h0-1+yy, w0-1+xx);
    }
    __syncthreads();

    unsigned long long acc[4][8];
    #pragma unroll
    for (int dz=0; dz<4; dz++)
        #pragma unroll
        for (int cp=0; cp<8; cp++) acc[dz][cp] = 0ull;

    const float* bx = sx + ty*34 + tx;
    #pragma unroll
    for (int kh=0; kh<3; kh++)
    #pragma unroll
    for (int kw=0; kw<3; kw++){
        unsigned long long x2[6];
        #pragma unroll
        for (int j=0; j<6; j++){
            float xv = bx[j*340 + kh*34 + kw];
            x2[j] = pack2(xv, xv);
        }
        #pragma unroll
        for (int kd=0; kd<3; kd++){
            const int k = (kd*3+kh)*3+kw;
            const ulonglong2* wp = reinterpret_cast<const ulonglong2*>(swt + k*8);
            #pragma unroll
            for (int jp=0; jp<4; jp++){
                ulonglong2 wv = wp[jp];
                #pragma unroll
                for (int dz=0; dz<4; dz++){
                    ffma2(acc[dz][2*jp],   x2[dz+kd], wv.x);
                    ffma2(acc[dz][2*jp+1], x2[dz+kd], wv.y);
                }
            }
        }
    }

    float bl[8], bh[8];
    #pragma unroll
    for (int cp=0; cp<8; cp++){ bl[cp] = b1[2*cp]; bh[cp] = b1[2*cp+1]; }

    #pragma unroll 1
    for (int dz=0; dz<4; dz++){
        __syncthreads();
        #pragma unroll
        for (int cp=0; cp<8; cp++){
            float lo, hi; unpack2(acc[dz][cp], lo, hi);
            sb[tid*8 + cp] = bf16x2(fmaxf(lo + bl[cp], 0.f),
                                    fmaxf(hi + bh[cp], 0.f));
        }
        __syncthreads();
        for (int j = tid; j < 2048; j += 256){     // 256 pos x 8 pairs (FIXED)
            int p = j >> 3, jj = j & 7;
            uint32_t v = sb[p*8 + jj];
            int h = p >> 5, w = p & 31;
            int pos = (((d0+dz)*Hh + h0+h)*Ww + w0+w);
            g_h1b[pos*8 + (jj&3)*2 + (jj>>2)] = v;   // permuted pair layout
        }
    }
}

// ================= shared A staging: halo tile copy (bf16, permuted) ===========
// A SMEM: 108 blocks (b = dhalo*18 + hhalo) x [w 10][16 ci bf16] = 320B/block.
// Permuted pair order makes (a0,a2) one lds_v2 at byte 8t and (a1,a3) at +320.
#define A_BYTES (108*320)                  // 34560
static __device__ __forceinline__ void stage_A(char* smem, const uint32_t* src,
                                               int tid, int w0, int h0, int d0){
    for (int i = tid; i < 2160; i += 256){
        int half = i & 1;
        int w = (i >> 1) % 10;
        int b = i / 20;
        int d = d0 - 1 + b/18;
        int h = h0 - 1 + b%18;
        int wg = w0 - 1 + w;
        uint4 v = make_uint4(0u,0u,0u,0u);
        if (d >= 0 && d < Dd && h >= 0 && h < Hh && wg >= 0 && wg < Ww)
            v = *reinterpret_cast<const uint4*>(src + (((d*Hh + h)*Ww + wg)*8 + half*4));
        *reinterpret_cast<uint4*>(smem + b*320 + w*32 + half*16) = v;
    }
}

// ================= conv2: 16 -> 16 via mma.sync bf16 (m16n8k16) ================
// CTA tile: 8(w) x 16(h) x 4(d), 16 co. 27 taps, K=16 (all ci per MMA).
// B SMEM: [tap 27][nt 2][lane 32] x 8B = 13824B.
#define B2_OFF  A_BYTES
#define CV2_SMEM (B2_OFF + 27*512)         // 48384

__global__ void __launch_bounds__(256,3) k_conv2m(const float* __restrict__ w2,
                                                  const float* __restrict__ b2){
    extern __shared__ char smem[];
    const int tid = threadIdx.x;
    const int wid = tid >> 5;
    const int lane = tid & 31;
    const int t = lane & 3, g = lane >> 2;
    const int w0 = blockIdx.x*8, h0 = blockIdx.y*16, d0 = blockIdx.z*4;

    stage_A(smem, g_h1b, tid, w0, h0, d0);
    for (int i = tid; i < 1728; i += 256){
        int l = i & 31, nt = (i >> 5) & 1, tap = i >> 6;
        int lt = l & 3, lg = l >> 2;
        const float* wp = w2 + ((nt*8 + lg)*16)*27 + tap;
        uint32_t v0 = bf16x2(wp[(2*lt  )*27], wp[(2*lt+1)*27]);
        uint32_t v1 = bf16x2(wp[(2*lt+8)*27], wp[(2*lt+9)*27]);
        *reinterpret_cast<uint2*>(smem + B2_OFF + tap*512 + nt*256 + l*8) = make_uint2(v0, v1);
    }
    __syncthreads();

    float acc[4][8];
    #pragma unroll
    for (int s=0; s<4; s++)
        #pragma unroll
        for (int j=0; j<8; j++) acc[s][j] = 0.f;

    const uint32_t sb_ = smem_u32(smem);
    const uint32_t a_base = sb_ + (uint32_t)(2*wid)*320u + (uint32_t)g*32u + (uint32_t)t*8u;
    const uint32_t b_base = sb_ + B2_OFF + (uint32_t)lane*8u;

    #pragma unroll 1
    for (int dh = 0; dh < 3; dh++){
        #pragma unroll
        for (int dw = 0; dw < 3; dw++){
            uint32_t bf[3][2][2];
            #pragma unroll
            for (int dd=0; dd<3; dd++)
                #pragma unroll
                for (int nt=0; nt<2; nt++)
                    lds_v2(b_base + (uint32_t)(dd*9+dh*3+dw)*512u + nt*256u,
                           bf[dd][nt][0], bf[dd][nt][1]);
            uint32_t ab = a_base + (uint32_t)dh*320u + (uint32_t)dw*32u;
            #pragma unroll
            for (int dblk=0; dblk<6; dblk++){
                uint32_t a0,a2,a1,a3;
                lds_v2(ab + (uint32_t)dblk*5760u,        a0, a2);
                lds_v2(ab + (uint32_t)dblk*5760u + 320u, a1, a3);
                #pragma unroll
                for (int dd=0; dd<3; dd++){
                    const int s = dblk - dd;
                    if (s >= 0 && s < 4){
                        mma_bf16(&acc[s][0], a0,a1,a2,a3, bf[dd][0][0], bf[dd][0][1]);
                        mma_bf16(&acc[s][4], a0,a1,a2,a3, bf[dd][1][0], bf[dd][1][1]);
                    }
                }
            }
        }
    }

    // epilogue: bias + relu, bf16x2 permuted stores to g_h2b
    #pragma unroll
    for (int nt = 0; nt < 2; nt++){
        float blv = b2[nt*8 + 2*t], bhv = b2[nt*8 + 2*t + 1];
        #pragma unroll
        for (int s = 0; s < 4; s++){
            int pos0 = ((d0+s)*Hh + h0 + 2*wid)*Ww + w0 + g;
            uint32_t v0 = bf16x2(fmaxf(acc[s][nt*4+0] + blv, 0.f),
                                 fmaxf(acc[s][nt*4+1] + bhv, 0.f));
            uint32_t v1 = bf16x2(fmaxf(acc[s][nt*4+2] + blv, 0.f),
                                 fmaxf(acc[s][nt*4+3] + bhv, 0.f));
            g_h2b[ pos0     *8 + t*2 + nt] = v0;   // row g   (h = 2wid)
            g_h2b[(pos0+Ww) *8 + t*2 + nt] = v1;   // row g+8 (h = 2wid+1)
        }
    }
}

// ================= conv3: 16 -> 1 via mma.sync bf16, fused updates =============
// Same GEMM as conv2 but N-tile=1, only col 0 of B nonzero. Lanes with t==0
// hold the results (c0: row g, c2: row g+8). Epilogue fuses residual + update.
#define B3_OFF  A_BYTES
#define CV3_SMEM (B3_OFF + 27*256)         // 41472

template<int A>
__global__ void __launch_bounds__(256,3) k_conv3m(const float* __restrict__ w3,
                                                  const float* __restrict__ b3,
                                                  const float* __restrict__ eta_arr,
                                                  int c){
    extern __shared__ char smem[];
    const int tid = threadIdx.x;
    const int wid = tid >> 5;
    const int lane = tid & 31;
    const int t = lane & 3, g = lane >> 2;
    const int w0 = blockIdx.x*8, h0 = blockIdx.y*16, d0 = blockIdx.z*4;

    stage_A(smem, g_h2b, tid, w0, h0, d0);
    for (int i = tid; i < 864; i += 256){
        int l = i & 31, tap = i >> 5;
        int lt = l & 3, lg = l >> 2;
        uint32_t v0 = 0u, v1 = 0u;
        if (lg == 0){
            v0 = bf16x2(w3[(2*lt  )*27 + tap], w3[(2*lt+1)*27 + tap]);
            v1 = bf16x2(w3[(2*lt+8)*27 + tap], w3[(2*lt+9)*27 + tap]);
        }
        *reinterpret_cast<uint2*>(smem + B3_OFF + tap*256 + l*8) = make_uint2(v0, v1);
    }
    __syncthreads();

    float acc[4][4];
    #pragma unroll
    for (int s=0; s<4; s++)
        #pragma unroll
        for (int j=0; j<4; j++) acc[s][j] = 0.f;

    const uint32_t sb_ = smem_u32(smem);
    const uint32_t a_base = sb_ + (uint32_t)(2*wid)*320u + (uint32_t)g*32u + (uint32_t)t*8u;
    const uint32_t b_base = sb_ + B3_OFF + (uint32_t)lane*8u;

    #pragma unroll 1
    for (int dh = 0; dh < 3; dh++){
        #pragma unroll
        for (int dw = 0; dw < 3; dw++){
            uint32_t bf[3][2];
            #pragma unroll
            for (int dd=0; dd<3; dd++)
                lds_v2(b_base + (uint32_t)(dd*9+dh*3+dw)*256u, bf[dd][0], bf[dd][1]);
            uint32_t ab = a_base + (uint32_t)dh*320u + (uint32_t)dw*32u;
            #pragma unroll
            for (int dblk=0; dblk<6; dblk++){
                uint32_t a0,a2,a1,a3;
                lds_v2(ab + (uint32_t)dblk*5760u,        a0, a2);
                lds_v2(ab + (uint32_t)dblk*5760u + 320u, a1, a3);
                #pragma unroll
                for (int dd=0; dd<3; dd++){
                    const int s = dblk - dd;
                    if (s >= 0 && s < 4)
                        mma_bf16(&acc[s][0], a0,a1,a2,a3, bf[dd][0], bf[dd][1]);
                }
            }
        }
    }

    // epilogue: residual + p/q/s/z' update on result-holding lanes (t == 0)
    if (t == 0){
        float* tgt        = (A==0) ? g_p : (A==1) ? g_q : (A==2) ? g_s : g_zp;
        const float* base = (A==3) ? g_t : tgt;
        const float eta = eta_arr[c];
        const float b3v = b3[0];
        #pragma unroll
        for (int s = 0; s < 4; s++){
            #pragma unroll
            for (int hl = 0; hl < 2; hl++){
                int d = d0 + s, h = h0 + 2*wid + hl, w = w0 + g;
                int idx = (d*Hh + h)*Ww + w;
                float nnew = getx<A>(d, h, w) + acc[s][hl*2] + b3v;
                tgt[idx] = (1.f + eta)*base[idx] - eta*nnew;
            }
        }
    }
}

// ---------------- update: t = fdT_w(p)+fdT_h(q)+fdT_d(s)+z', write out --------
__global__ void k_update(float* __restrict__ outp){
    int idx = blockIdx.x*256 + threadIdx.x;
    int w = idx & (Ww-1);
    int h = (idx >> 7) & (Hh-1);
    int d = idx >> 14;
    float fa = (w==Ww-1) ? g_p[idx-1]  : ((w>0 ? g_p[idx-1]  : 0.f) - g_p[idx]);
    float fb = (h==Hh-1) ? g_q[idx-Ww] : ((h>0 ? g_q[idx-Ww] : 0.f) - g_q[idx]);
    float fc = (d==Dd-1) ? g_s[idx-HW] : ((d>0 ? g_s[idx-HW] : 0.f) - g_s[idx]);
    float tn = fa + fb + fc + g_zp[idx];
    g_t[idx] = tn;
    outp[idx] = tn;
}

// ---------------- launcher -----------------------------------------------------
extern "C" void kernel_launch(void* const* d_in, const int* in_sizes, int n_in,
                              void* d_out, int out_size){
    (void)in_sizes; (void)n_in; (void)out_size;
    const float* img  = (const float*)d_in[0];
    const float* sino = (const float*)d_in[1];
    const float* w1   = (const float*)d_in[2];
    const float* b1   = (const float*)d_in[3];
    const float* w2   = (const float*)d_in[4];
    const float* b2   = (const float*)d_in[5];
    const float* w3   = (const float*)d_in[6];
    const float* b3   = (const float*)d_in[7];
    const float* ntx  = (const float*)d_in[8];
    const float* nty  = (const float*)d_in[9];
    const float* ntz  = (const float*)d_in[10];
    const float* nt   = (const float*)d_in[11];
    float* out = (float*)d_out;

    dim3 cg(4, 16, 16), cb(32, 8, 1);
    dim3 g2(16, 8, 16);                 // w/8, h/16, d/4
    k_init<<<NN/256, 256>>>(img, out);
    for (int c = 0; c < 3; c++){
        k_colsum<<<HW/256, 256>>>();
        k_z<<<NN/256, 256>>>(sino);

        k_conv1<0><<<cg, cb>>>(w1 + 0*432, b1 + 0*16);
        k_conv2m<<<g2, 256, CV2_SMEM>>>(w2 + 0*6912, b2 + 0*16);
        k_conv3m<0><<<g2, 256, CV3_SMEM>>>(w3 + 0*432, b3 + 0, ntx, c);

        k_conv1<1><<<cg, cb>>>(w1 + 1*432, b1 + 1*16);
        k_conv2m<<<g2, 256, CV2_SMEM>>>(w2 + 1*6912, b2 + 1*16);
        k_conv3m<1><<<g2, 256, CV3_SMEM>>>(w3 + 1*432, b3 + 1, nty, c);

        k_conv1<2><<<cg, cb>>>(w1 + 2*432, b1 + 2*16);
        k_conv2m<<<g2, 256, CV2_SMEM>>>(w2 + 2*6912, b2 + 2*16);
        k_conv3m<2><<<g2, 256, CV3_SMEM>>>(w3 + 2*432, b3 + 2, ntz, c);

        k_conv1<3><<<cg, cb>>>(w1 + 3*432, b1 + 3*16);
        k_conv2m<<<g2, 256, CV2_SMEM>>>(w2 + 3*6912, b2 + 3*16);
        k_conv3m<3><<<g2, 256, CV3_SMEM>>>(w3 + 3*432, b3 + 3, nt, c);

        k_update<<<NN/256, 256>>>(out + (c+1)*NN);
    }
}

// round 9
// speedup vs baseline: 6.6526x; 1.1720x over previous
#include <cuda_runtime.h>
#include <cstdint>

#define Dd 64
#define Hh 128
#define Ww 128
#define HW (Hh*Ww)
#define NN (Dd*Hh*Ww)

// ---------------- scratch (device globals: alloc-free, capture-safe) ----------
__device__ float g_t[NN];
__device__ float g_z[NN];
__device__ float g_p[NN];
__device__ float g_q[NN];
__device__ float g_s[NN];
__device__ float g_zp[NN];
__device__ float g_sums[HW];
// bf16 intermediates, channel-interleaved + ci-pair permuted:
//   u32 index = pos*8 + (j&3)*2 + (j>>2), where j = ci>>1 (pair index)
__device__ uint32_t g_h1b[8*NN];
__device__ uint32_t g_h2b[8*NN];

// ---------------- bf16 / mma.sync helpers (family-safe PTX) ---------------------
static __device__ __forceinline__ uint32_t smem_u32(const void* p){
    uint32_t a;
    asm("{ .reg .u64 t; cvta.to.shared.u64 t, %1; cvt.u32.u64 %0, t; }" : "=r"(a) : "l"(p));
    return a;
}
static __device__ __forceinline__ uint32_t bf16x2(float lo, float hi){
    uint32_t r;
    asm("cvt.rn.bf16x2.f32 %0, %1, %2;" : "=r"(r) : "f"(hi), "f"(lo));
    return r;
}
static __device__ __forceinline__ void lds_v2(uint32_t addr, uint32_t &x, uint32_t &y){
    asm volatile("ld.shared.v2.u32 {%0,%1}, [%2];" : "=r"(x), "=r"(y) : "r"(addr));
}
static __device__ __forceinline__ void mma_bf16(float* c, uint32_t a0, uint32_t a1,
                                                uint32_t a2, uint32_t a3,
                                                uint32_t b0, uint32_t b1){
    asm volatile(
        "mma.sync.aligned.m16n8k16.row.col.f32.bf16.bf16.f32 "
        "{%0,%1,%2,%3}, {%4,%5,%6,%7}, {%8,%9}, {%0,%1,%2,%3};"
        : "+f"(c[0]), "+f"(c[1]), "+f"(c[2]), "+f"(c[3])
        : "r"(a0), "r"(a1), "r"(a2), "r"(a3), "r"(b0), "r"(b1));
}

// x = fdiff(z, axis) on the fly (0:W, 1:H, 2:D, 3:identity)
template<int MODE>
static __device__ __forceinline__ float getx(int d, int h, int w){
    if (d < 0 || d >= Dd || h < 0 || h >= Hh || w < 0 || w >= Ww) return 0.f;
    int idx = (d*Hh + h)*Ww + w;
    if (MODE == 0) return (w < Ww-1) ? g_z[idx+1]  - g_z[idx] : 0.f;
    if (MODE == 1) return (h < Hh-1) ? g_z[idx+Ww] - g_z[idx] : 0.f;
    if (MODE == 2) return (d < Dd-1) ? g_z[idx+HW] - g_z[idx] : 0.f;
    return g_z[idx];
}

// ---------------- init / colsum / z ---------------------------------------------
__global__ void k_init(const float* __restrict__ img, float* __restrict__ outp){
    int idx = blockIdx.x*256 + threadIdx.x;
    float v = img[idx];
    g_t[idx] = v;
    outp[idx] = v;
    g_p[idx] = 0.f; g_q[idx] = 0.f; g_s[idx] = 0.f;
}
__global__ void k_colsum(){
    int j = blockIdx.x*256 + threadIdx.x;
    float a0=0.f, a1=0.f, a2=0.f, a3=0.f;
    #pragma unroll
    for (int d = 0; d < Dd; d += 4){
        a0 += g_t[(d+0)*HW + j];
        a1 += g_t[(d+1)*HW + j];
        a2 += g_t[(d+2)*HW + j];
        a3 += g_t[(d+3)*HW + j];
    }
    g_sums[j] = (a0+a1)+(a2+a3);
}
__global__ void k_z(const float* __restrict__ sino){
    int idx = blockIdx.x*256 + threadIdx.x;
    int j = idx & (HW-1);
    g_z[idx] = g_t[idx] + (sino[j] - g_sums[j]) * (1.f/64.f);
}

// ================= conv1: 1 -> 16 via mma.sync bf16, taps on K =================
// GEMM: D[M=512 spatial][16 co] = A[M][K=32 (27 taps padded)] x W[K][16].
// CTA tile 8w x 16h x 4d; warp wid owns hh in {2wid, 2wid+1}, all 4 d-slices.
// A fragments built per-lane directly from the x-halo tile in SMEM.
template<int MODE>
__global__ void __launch_bounds__(256) k_conv1m(const float* __restrict__ w1,
                                                const float* __restrict__ b1){
    __shared__ float sx[1296];                // [dz 6][h 18][w 12 (10 used)]
    const int tid = threadIdx.x;
    const int wid = tid >> 5;
    const int lane = tid & 31;
    const int t = lane & 3, g = lane >> 2;
    const int w0 = blockIdx.x*8, h0 = blockIdx.y*16, d0 = blockIdx.z*4;

    // stage x halo tile (fdiff of z on the fly)
    for (int i = tid; i < 1296; i += 256){
        int w = i % 12; int r = i / 12;
        int h = r % 18; int dz = r / 18;
        float v = 0.f;
        if (w < 10) v = getx<MODE>(d0-1+dz, h0-1+h, w0-1+w);
        sx[i] = v;
    }

    // weight fragments straight from gmem (col g, k = ks*16 + {2t,2t+1,2t+8,2t+9})
    uint2 B[2][2];
    #pragma unroll
    for (int ks=0; ks<2; ks++)
        #pragma unroll
        for (int nt=0; nt<2; nt++){
            const float* wp = w1 + (nt*8 + g)*27;
            int k0 = ks*16 + 2*t;
            float f0 = (k0   < 27) ? wp[k0  ] : 0.f;
            float f1 = (k0+1 < 27) ? wp[k0+1] : 0.f;
            float f8 = (k0+8 < 27) ? wp[k0+8] : 0.f;
            float f9 = (k0+9 < 27) ? wp[k0+9] : 0.f;
            B[ks][nt] = make_uint2(bf16x2(f0,f1), bf16x2(f8,f9));
        }

    // per-lane tap offsets for the 8 A-fragment k-values
    int off[8]; bool vv[8];
    #pragma unroll
    for (int j=0; j<8; j++){
        int k = 2*t + (j&1) + ((j>>1)&1)*8 + (j>>2)*16;
        vv[j] = (k < 27);
        int kk = vv[j] ? k : 0;
        int dd = kk/9, rem = kk - dd*9;
        int dh = rem/3, dw = rem - dh*3;
        off[j] = dd*216 + dh*12 + dw;
    }
    __syncthreads();

    float acc[4][8];
    #pragma unroll
    for (int s=0; s<4; s++)
        #pragma unroll
        for (int j=0; j<8; j++) acc[s][j] = 0.f;

    const float* sxp = sx + (2*wid)*12 + g;
    #pragma unroll
    for (int s=0; s<4; s++){
        const float* p0 = sxp + s*216;        // row g   (hh = 2wid)
        const float* p1 = p0 + 12;            // row g+8 (hh = 2wid+1)
        float x0[8], x1[8];
        #pragma unroll
        for (int j=0; j<8; j++){
            x0[j] = vv[j] ? p0[off[j]] : 0.f;
            x1[j] = vv[j] ? p1[off[j]] : 0.f;
        }
        uint32_t a0 = bf16x2(x0[0],x0[1]), a1 = bf16x2(x1[0],x1[1]);
        uint32_t a2 = bf16x2(x0[2],x0[3]), a3 = bf16x2(x1[2],x1[3]);
        uint32_t c0 = bf16x2(x0[4],x0[5]), c1 = bf16x2(x1[4],x1[5]);
        uint32_t c2 = bf16x2(x0[6],x0[7]), c3 = bf16x2(x1[6],x1[7]);
        #pragma unroll
        for (int nt=0; nt<2; nt++){
            mma_bf16(&acc[s][nt*4], a0,a1,a2,a3, B[0][nt].x, B[0][nt].y);
            mma_bf16(&acc[s][nt*4], c0,c1,c2,c3, B[1][nt].x, B[1][nt].y);
        }
    }

    // epilogue: bias + relu, bf16x2 permuted stores to g_h1b
    #pragma unroll
    for (int nt = 0; nt < 2; nt++){
        float blv = b1[nt*8 + 2*t], bhv = b1[nt*8 + 2*t + 1];
        #pragma unroll
        for (int s = 0; s < 4; s++){
            int pos0 = ((d0+s)*Hh + h0 + 2*wid)*Ww + w0 + g;
            uint32_t v0 = bf16x2(fmaxf(acc[s][nt*4+0] + blv, 0.f),
                                 fmaxf(acc[s][nt*4+1] + bhv, 0.f));
            uint32_t v1 = bf16x2(fmaxf(acc[s][nt*4+2] + blv, 0.f),
                                 fmaxf(acc[s][nt*4+3] + bhv, 0.f));
            g_h1b[ pos0     *8 + t*2 + nt] = v0;
            g_h1b[(pos0+Ww) *8 + t*2 + nt] = v1;
        }
    }
}

// ================= shared A staging: halo tile copy (bf16, permuted) ===========
// A SMEM: 108 blocks (b = dhalo*18 + hhalo) x [w 10][16 ci bf16] = 320B/block.
#define A_BYTES (108*320)                  // 34560
static __device__ __forceinline__ void stage_A(char* smem, const uint32_t* src,
                                               int tid, int w0, int h0, int d0){
    for (int i = tid; i < 2160; i += 256){
        int half = i & 1;
        int w = (i >> 1) % 10;
        int b = i / 20;
        int d = d0 - 1 + b/18;
        int h = h0 - 1 + b%18;
        int wg = w0 - 1 + w;
        uint4 v = make_uint4(0u,0u,0u,0u);
        if (d >= 0 && d < Dd && h >= 0 && h < Hh && wg >= 0 && wg < Ww)
            v = *reinterpret_cast<const uint4*>(src + (((d*Hh + h)*Ww + wg)*8 + half*4));
        *reinterpret_cast<uint4*>(smem + b*320 + w*32 + half*16) = v;
    }
}

// ================= conv2: 16 -> 16 via mma.sync bf16 (m16n8k16) ================
#define B2_OFF  A_BYTES
#define CV2_SMEM (B2_OFF + 27*512)         // 48384

__global__ void __launch_bounds__(256,3) k_conv2m(const float* __restrict__ w2,
                                                  const float* __restrict__ b2){
    extern __shared__ char smem[];
    const int tid = threadIdx.x;
    const int wid = tid >> 5;
    const int lane = tid & 31;
    const int t = lane & 3, g = lane >> 2;
    const int w0 = blockIdx.x*8, h0 = blockIdx.y*16, d0 = blockIdx.z*4;

    stage_A(smem, g_h1b, tid, w0, h0, d0);
    for (int i = tid; i < 1728; i += 256){
        int l = i & 31, nt = (i >> 5) & 1, tap = i >> 6;
        int lt = l & 3, lg = l >> 2;
        const float* wp = w2 + ((nt*8 + lg)*16)*27 + tap;
        uint32_t v0 = bf16x2(wp[(2*lt  )*27], wp[(2*lt+1)*27]);
        uint32_t v1 = bf16x2(wp[(2*lt+8)*27], wp[(2*lt+9)*27]);
        *reinterpret_cast<uint2*>(smem + B2_OFF + tap*512 + nt*256 + l*8) = make_uint2(v0, v1);
    }
    __syncthreads();

    float acc[4][8];
    #pragma unroll
    for (int s=0; s<4; s++)
        #pragma unroll
        for (int j=0; j<8; j++) acc[s][j] = 0.f;

    const uint32_t sb_ = smem_u32(smem);
    const uint32_t a_base = sb_ + (uint32_t)(2*wid)*320u + (uint32_t)g*32u + (uint32_t)t*8u;
    const uint32_t b_base = sb_ + B2_OFF + (uint32_t)lane*8u;

    #pragma unroll 1
    for (int dh = 0; dh < 3; dh++){
        #pragma unroll
        for (int dw = 0; dw < 3; dw++){
            uint32_t bf[3][2][2];
            #pragma unroll
            for (int dd=0; dd<3; dd++)
                #pragma unroll
                for (int nt=0; nt<2; nt++)
                    lds_v2(b_base + (uint32_t)(dd*9+dh*3+dw)*512u + nt*256u,
                           bf[dd][nt][0], bf[dd][nt][1]);
            uint32_t ab = a_base + (uint32_t)dh*320u + (uint32_t)dw*32u;
            #pragma unroll
            for (int dblk=0; dblk<6; dblk++){
                uint32_t a0,a2,a1,a3;
                lds_v2(ab + (uint32_t)dblk*5760u,        a0, a2);
                lds_v2(ab + (uint32_t)dblk*5760u + 320u, a1, a3);
                #pragma unroll
                for (int dd=0; dd<3; dd++){
                    const int s = dblk - dd;
                    if (s >= 0 && s < 4){
                        mma_bf16(&acc[s][0], a0,a1,a2,a3, bf[dd][0][0], bf[dd][0][1]);
                        mma_bf16(&acc[s][4], a0,a1,a2,a3, bf[dd][1][0], bf[dd][1][1]);
                    }
                }
            }
        }
    }

    #pragma unroll
    for (int nt = 0; nt < 2; nt++){
        float blv = b2[nt*8 + 2*t], bhv = b2[nt*8 + 2*t + 1];
        #pragma unroll
        for (int s = 0; s < 4; s++){
            int pos0 = ((d0+s)*Hh + h0 + 2*wid)*Ww + w0 + g;
            uint32_t v0 = bf16x2(fmaxf(acc[s][nt*4+0] + blv, 0.f),
                                 fmaxf(acc[s][nt*4+1] + bhv, 0.f));
            uint32_t v1 = bf16x2(fmaxf(acc[s][nt*4+2] + blv, 0.f),
                                 fmaxf(acc[s][nt*4+3] + bhv, 0.f));
            g_h2b[ pos0     *8 + t*2 + nt] = v0;
            g_h2b[(pos0+Ww) *8 + t*2 + nt] = v1;
        }
    }
}

// ================= conv3: 16 -> 1 via mma.sync bf16, fused updates =============
#define B3_OFF  A_BYTES
#define CV3_SMEM (B3_OFF + 27*256)         // 41472

template<int A>
__global__ void __launch_bounds__(256,3) k_conv3m(const float* __restrict__ w3,
                                                  const float* __restrict__ b3,
                                                  const float* __restrict__ eta_arr,
                                                  int c){
    extern __shared__ char smem[];
    const int tid = threadIdx.x;
    const int wid = tid >> 5;
    const int lane = tid & 31;
    const int t = lane & 3, g = lane >> 2;
    const int w0 = blockIdx.x*8, h0 = blockIdx.y*16, d0 = blockIdx.z*4;

    stage_A(smem, g_h2b, tid, w0, h0, d0);
    for (int i = tid; i < 864; i += 256){
        int l = i & 31, tap = i >> 5;
        int lt = l & 3, lg = l >> 2;
        uint32_t v0 = 0u, v1 = 0u;
        if (lg == 0){
            v0 = bf16x2(w3[(2*lt  )*27 + tap], w3[(2*lt+1)*27 + tap]);
            v1 = bf16x2(w3[(2*lt+8)*27 + tap], w3[(2*lt+9)*27 + tap]);
        }
        *reinterpret_cast<uint2*>(smem + B3_OFF + tap*256 + l*8) = make_uint2(v0, v1);
    }
    __syncthreads();

    float acc[4][4];
    #pragma unroll
    for (int s=0; s<4; s++)
        #pragma unroll
        for (int j=0; j<4; j++) acc[s][j] = 0.f;

    const uint32_t sb_ = smem_u32(smem);
    const uint32_t a_base = sb_ + (uint32_t)(2*wid)*320u + (uint32_t)g*32u + (uint32_t)t*8u;
    const uint32_t b_base = sb_ + B3_OFF + (uint32_t)lane*8u;

    #pragma unroll 1
    for (int dh = 0; dh < 3; dh++){
        #pragma unroll
        for (int dw = 0; dw < 3; dw++){
            uint32_t bf[3][2];
            #pragma unroll
            for (int dd=0; dd<3; dd++)
                lds_v2(b_base + (uint32_t)(dd*9+dh*3+dw)*256u, bf[dd][0], bf[dd][1]);
            uint32_t ab = a_base + (uint32_t)dh*320u + (uint32_t)dw*32u;
            #pragma unroll
            for (int dblk=0; dblk<6; dblk++){
                uint32_t a0,a2,a1,a3;
                lds_v2(ab + (uint32_t)dblk*5760u,        a0, a2);
                lds_v2(ab + (uint32_t)dblk*5760u + 320u, a1, a3);
                #pragma unroll
                for (int dd=0; dd<3; dd++){
                    const int s = dblk - dd;
                    if (s >= 0 && s < 4)
                        mma_bf16(&acc[s][0], a0,a1,a2,a3, bf[dd][0], bf[dd][1]);
                }
            }
        }
    }

    if (t == 0){
        float* tgt        = (A==0) ? g_p : (A==1) ? g_q : (A==2) ? g_s : g_zp;
        const float* base = (A==3) ? g_t : tgt;
        const float eta = eta_arr[c];
        const float b3v = b3[0];
        #pragma unroll
        for (int s = 0; s < 4; s++){
            #pragma unroll
            for (int hl = 0; hl < 2; hl++){
                int d = d0 + s, h = h0 + 2*wid + hl, w = w0 + g;
                int idx = (d*Hh + h)*Ww + w;
                float nnew = getx<A>(d, h, w) + acc[s][hl*2] + b3v;
                tgt[idx] = (1.f + eta)*base[idx] - eta*nnew;
            }
        }
    }
}

// ---------------- update: t = fdT_w(p)+fdT_h(q)+fdT_d(s)+z', write out --------
__global__ void k_update(float* __restrict__ outp){
    int idx = blockIdx.x*256 + threadIdx.x;
    int w = idx & (Ww-1);
    int h = (idx >> 7) & (Hh-1);
    int d = idx >> 14;
    float fa = (w==Ww-1) ? g_p[idx-1]  : ((w>0 ? g_p[idx-1]  : 0.f) - g_p[idx]);
    float fb = (h==Hh-1) ? g_q[idx-Ww] : ((h>0 ? g_q[idx-Ww] : 0.f) - g_q[idx]);
    float fc = (d==Dd-1) ? g_s[idx-HW] : ((d>0 ? g_s[idx-HW] : 0.f) - g_s[idx]);
    float tn = fa + fb + fc + g_zp[idx];
    g_t[idx] = tn;
    outp[idx] = tn;
}

// ---------------- launcher -----------------------------------------------------
extern "C" void kernel_launch(void* const* d_in, const int* in_sizes, int n_in,
                              void* d_out, int out_size){
    (void)in_sizes; (void)n_in; (void)out_size;
    const float* img  = (const float*)d_in[0];
    const float* sino = (const float*)d_in[1];
    const float* w1   = (const float*)d_in[2];
    const float* b1   = (const float*)d_in[3];
    const float* w2   = (const float*)d_in[4];
    const float* b2   = (const float*)d_in[5];
    const float* w3   = (const float*)d_in[6];
    const float* b3   = (const float*)d_in[7];
    const float* ntx  = (const float*)d_in[8];
    const float* nty  = (const float*)d_in[9];
    const float* ntz  = (const float*)d_in[10];
    const float* nt   = (const float*)d_in[11];
    float* out = (float*)d_out;

    dim3 g2(16, 8, 16);                 // w/8, h/16, d/4
    k_init<<<NN/256, 256>>>(img, out);
    for (int c = 0; c < 3; c++){
        k_colsum<<<HW/256, 256>>>();
        k_z<<<NN/256, 256>>>(sino);

        k_conv1m<0><<<g2, 256>>>(w1 + 0*432, b1 + 0*16);
        k_conv2m<<<g2, 256, CV2_SMEM>>>(w2 + 0*6912, b2 + 0*16);
        k_conv3m<0><<<g2, 256, CV3_SMEM>>>(w3 + 0*432, b3 + 0, ntx, c);

        k_conv1m<1><<<g2, 256>>>(w1 + 1*432, b1 + 1*16);
        k_conv2m<<<g2, 256, CV2_SMEM>>>(w2 + 1*6912, b2 + 1*16);
        k_conv3m<1><<<g2, 256, CV3_SMEM>>>(w3 + 1*432, b3 + 1, nty, c);

        k_conv1m<2><<<g2, 256>>>(w1 + 2*432, b1 + 2*16);
        k_conv2m<<<g2, 256, CV2_SMEM>>>(w2 + 2*6912, b2 + 2*16);
        k_conv3m<2><<<g2, 256, CV3_SMEM>>>(w3 + 2*432, b3 + 2, ntz, c);

        k_conv1m<3><<<g2, 256>>>(w1 + 3*432, b1 + 3*16);
        k_conv2m<<<g2, 256, CV2_SMEM>>>(w2 + 3*6912, b2 + 3*16);
        k_conv3m<3><<<g2, 256, CV3_SMEM>>>(w3 + 3*432, b3 + 3, nt, c);

        k_update<<<NN/256, 256>>>(out + (c+1)*NN);
    }
}